// round 1
// baseline (speedup 1.0000x reference)
#include <cuda_runtime.h>
#include <math.h>

#define TOKENS 2048
#define DIM    512
#define NEXP   16
#define HID    2048
#define NSLOTS (TOKENS*2)
#define TM     64
#define TN     128
#define KC     16
#define MAX_TILES 80   // sum ceil(cnt_e/64) <= 4096/64 + 16 = 80

// ---------------- device scratch (no allocation allowed) ----------------
__device__ int   g_cnt[NEXP];
__device__ int   g_list[NEXP * TOKENS];   // slot = t*2+k, bucketed per expert
__device__ float g_wk[NSLOTS];            // gate weight per (t,k)
__device__ int   g_tiles[MAX_TILES];      // (e<<16) | mtile
__device__ int   g_ntiles;
__device__ float g_mu[NSLOTS];
__device__ float g_rs[NSLOTS];
__device__ float g_hbuf[(size_t)NSLOTS * HID];  // 33.5 MB
__device__ float g_ybuf[(size_t)NSLOTS * DIM];  //  8.4 MB

// ---------------- f32x2 packed-FMA helpers ----------------
__device__ __forceinline__ void ffma2(unsigned long long &c, unsigned long long a,
                                      unsigned long long b) {
    asm volatile("fma.rn.f32x2 %0, %1, %2, %0;" : "+l"(c) : "l"(a), "l"(b));
}
__device__ __forceinline__ unsigned long long splat2(float a) {
    unsigned long long r;
    asm("mov.b64 %0, {%1, %1};" : "=l"(r) : "f"(a));
    return r;
}
__device__ __forceinline__ unsigned long long pk2(float x, float y) {
    unsigned long long r;
    asm("mov.b64 %0, {%1, %2};" : "=l"(r) : "f"(x), "f"(y));
    return r;
}
__device__ __forceinline__ float2 unpk2(unsigned long long v) {
    float2 r;
    asm("mov.b64 {%0, %1}, %2;" : "=f"(r.x), "=f"(r.y) : "l"(v));
    return r;
}
__device__ __forceinline__ float silu(float v) {
    return v * (1.f / (1.f + __expf(-v)));
}

// ---------------- kernels ----------------
__global__ void init_kernel() {
    if (threadIdx.x < NEXP) g_cnt[threadIdx.x] = 0;
}

// one warp per token: lanes 0..15 each compute one expert logit, then top-2 + softmax
__global__ __launch_bounds__(256) void route_kernel(const float* __restrict__ x,
                                                    const float* __restrict__ Wg) {
    int t = (blockIdx.x * blockDim.x + threadIdx.x) >> 5;
    int lane = threadIdx.x & 31;
    if (t >= TOKENS) return;
    const float* xr = x + (size_t)t * DIM;
    float acc = 0.f;
    if (lane < NEXP) {
#pragma unroll 8
        for (int d = 0; d < DIM; d++) acc = fmaf(xr[d], Wg[d * NEXP + lane], acc);
    }
    float v0 = -1e30f, v1 = -1e30f;
    int i0 = 0, i1 = 0;
#pragma unroll
    for (int i = 0; i < NEXP; i++) {
        float vi = __shfl_sync(0xffffffffu, acc, i);
        if (vi > v0)      { v1 = v0; i1 = i0; v0 = vi; i0 = i; }
        else if (vi > v1) { v1 = vi; i1 = i; }
    }
    if (lane == 0) {
        float e1 = __expf(v1 - v0);   // v1 <= v0
        float s  = 1.f + e1;
        g_wk[t * 2 + 0] = 1.f / s;
        g_wk[t * 2 + 1] = e1 / s;
        int p0 = atomicAdd(&g_cnt[i0], 1);
        g_list[i0 * TOKENS + p0] = t * 2 + 0;
        int p1 = atomicAdd(&g_cnt[i1], 1);
        g_list[i1 * TOKENS + p1] = t * 2 + 1;
    }
}

__global__ void tilelist_kernel() {
    if (threadIdx.x == 0) {
        int nt = 0;
        for (int e = 0; e < NEXP; e++) {
            int c = g_cnt[e];
            int mt = (c + TM - 1) / TM;
            for (int m = 0; m < mt; m++) g_tiles[nt++] = (e << 16) | m;
        }
        g_ntiles = nt;
    }
}

// GEMM1: hbuf[slot][n] = silu(x[t] @ W1[e] + b1[e])   (K=DIM=512, N=HID)
__global__ __launch_bounds__(256) void gemm1_kernel(const float* __restrict__ x,
                                                    const float* __restrict__ W1,
                                                    const float* __restrict__ b1) {
    __shared__ __align__(16) float As[KC][68];
    __shared__ __align__(16) float Bs[KC][136];
    __shared__ int s_slot[TM];
    int tile = blockIdx.y;
    if (tile >= g_ntiles) return;
    int info = g_tiles[tile];
    int e = info >> 16;
    int m0 = (info & 0xffff) * TM;
    int n0 = blockIdx.x * TN;
    int cnt = g_cnt[e];
    int tid = threadIdx.x;
    if (tid < TM) {
        int r = m0 + tid;
        s_slot[tid] = (r < cnt) ? g_list[e * TOKENS + r] : -1;
    }
    __syncthreads();
    const int tx = tid & 15, ty = tid >> 4;
    const int lm = tid >> 2, lkq = tid & 3;
    const int lk = tid >> 4, lnq = tid & 15;
    int sA = s_slot[lm]; if (sA < 0) sA = s_slot[0];
    const float* aptr = x + (size_t)(sA >> 1) * DIM + lkq * 4;
    const float* bptr = W1 + (size_t)e * DIM * HID + (size_t)lk * HID + n0 + lnq * 4;

    unsigned long long c[4][4];
#pragma unroll
    for (int i = 0; i < 4; i++)
#pragma unroll
        for (int j = 0; j < 4; j++) c[i][j] = 0ull;

    for (int k0 = 0; k0 < DIM; k0 += KC) {
        float4 a4  = *(const float4*)(aptr + k0);
        float4 b40 = *(const float4*)(bptr);
        float4 b41 = *(const float4*)(bptr + 64);
        bptr += (size_t)KC * HID;
        __syncthreads();
        As[lkq * 4 + 0][lm] = a4.x;
        As[lkq * 4 + 1][lm] = a4.y;
        As[lkq * 4 + 2][lm] = a4.z;
        As[lkq * 4 + 3][lm] = a4.w;
        *(float4*)&Bs[lk][lnq * 4]      = b40;
        *(float4*)&Bs[lk][64 + lnq * 4] = b41;
        __syncthreads();
#pragma unroll
        for (int k = 0; k < KC; k++) {
            float4 a  = *(const float4*)&As[k][ty * 4];
            float4 bA = *(const float4*)&Bs[k][tx * 4];
            float4 bB = *(const float4*)&Bs[k][64 + tx * 4];
            unsigned long long q0 = pk2(bA.x, bA.y), q1 = pk2(bA.z, bA.w);
            unsigned long long q2 = pk2(bB.x, bB.y), q3 = pk2(bB.z, bB.w);
            float am[4] = {a.x, a.y, a.z, a.w};
#pragma unroll
            for (int mj = 0; mj < 4; mj++) {
                unsigned long long s = splat2(am[mj]);
                ffma2(c[mj][0], s, q0);
                ffma2(c[mj][1], s, q1);
                ffma2(c[mj][2], s, q2);
                ffma2(c[mj][3], s, q3);
            }
        }
    }
    float4 bb0 = *(const float4*)&b1[e * HID + n0 + tx * 4];
    float4 bb1 = *(const float4*)&b1[e * HID + n0 + 64 + tx * 4];
#pragma unroll
    for (int mj = 0; mj < 4; mj++) {
        int slot = s_slot[ty * 4 + mj];
        if (slot < 0) continue;
        float2 v0 = unpk2(c[mj][0]);
        float2 v1 = unpk2(c[mj][1]);
        float2 v2 = unpk2(c[mj][2]);
        float2 v3 = unpk2(c[mj][3]);
        float4 o0 = make_float4(silu(v0.x + bb0.x), silu(v0.y + bb0.y),
                                silu(v1.x + bb0.z), silu(v1.y + bb0.w));
        float4 o1 = make_float4(silu(v2.x + bb1.x), silu(v2.y + bb1.y),
                                silu(v3.x + bb1.z), silu(v3.y + bb1.w));
        float* hrow = g_hbuf + (size_t)slot * HID + n0;
        *(float4*)&hrow[tx * 4]      = o0;
        *(float4*)&hrow[64 + tx * 4] = o1;
    }
}

// per-slot LayerNorm stats over H=2048
__global__ __launch_bounds__(256) void lnstats_kernel() {
    __shared__ float ss[8], sq[8];
    int slot = blockIdx.x;
    const float* h = g_hbuf + (size_t)slot * HID;
    int tid = threadIdx.x;
    float s = 0.f, q = 0.f;
#pragma unroll
    for (int i = 0; i < 2; i++) {
        float4 v = *(const float4*)&h[(tid + i * 256) * 4];
        s += v.x + v.y + v.z + v.w;
        q += v.x * v.x + v.y * v.y + v.z * v.z + v.w * v.w;
    }
#pragma unroll
    for (int o = 16; o > 0; o >>= 1) {
        s += __shfl_down_sync(0xffffffffu, s, o);
        q += __shfl_down_sync(0xffffffffu, q, o);
    }
    if ((tid & 31) == 0) { ss[tid >> 5] = s; sq[tid >> 5] = q; }
    __syncthreads();
    if (tid == 0) {
        s = ss[0]; q = sq[0];
        for (int i = 1; i < 8; i++) { s += ss[i]; q += sq[i]; }
        float mu  = s * (1.f / HID);
        float var = q * (1.f / HID) - mu * mu;
        g_mu[slot] = mu;
        g_rs[slot] = rsqrtf(var + 1e-5f);
    }
}

// GEMM2: ybuf[slot][n] = LN(hbuf[slot]) @ W2[e] + b2[e]   (K=HID=2048, N=DIM)
__global__ __launch_bounds__(256) void gemm2_kernel(const float* __restrict__ W2,
                                                    const float* __restrict__ b2,
                                                    const float* __restrict__ ln_g,
                                                    const float* __restrict__ ln_b) {
    __shared__ __align__(16) float As[KC][68];
    __shared__ __align__(16) float Bs[KC][136];
    __shared__ int s_slot[TM];
    int tile = blockIdx.y;
    if (tile >= g_ntiles) return;
    int info = g_tiles[tile];
    int e = info >> 16;
    int m0 = (info & 0xffff) * TM;
    int n0 = blockIdx.x * TN;
    int cnt = g_cnt[e];
    int tid = threadIdx.x;
    if (tid < TM) {
        int r = m0 + tid;
        s_slot[tid] = (r < cnt) ? g_list[e * TOKENS + r] : -1;
    }
    __syncthreads();
    const int tx = tid & 15, ty = tid >> 4;
    const int lm = tid >> 2, lkq = tid & 3;
    const int lk = tid >> 4, lnq = tid & 15;
    int sA = s_slot[lm]; if (sA < 0) sA = s_slot[0];
    float mu = g_mu[sA];
    float rs = g_rs[sA];
    const float* aptr = g_hbuf + (size_t)sA * HID + lkq * 4;
    const float* gptr = ln_g + (size_t)e * HID + lkq * 4;
    const float* bptrln = ln_b + (size_t)e * HID + lkq * 4;
    const float* bptr = W2 + (size_t)e * HID * DIM + (size_t)lk * DIM + n0 + lnq * 4;

    unsigned long long c[4][4];
#pragma unroll
    for (int i = 0; i < 4; i++)
#pragma unroll
        for (int j = 0; j < 4; j++) c[i][j] = 0ull;

    for (int k0 = 0; k0 < HID; k0 += KC) {
        float4 h4 = *(const float4*)(aptr + k0);
        float4 g4 = *(const float4*)(gptr + k0);
        float4 l4 = *(const float4*)(bptrln + k0);
        float4 b40 = *(const float4*)(bptr);
        float4 b41 = *(const float4*)(bptr + 64);
        bptr += (size_t)KC * DIM;
        float4 a4;
        a4.x = (h4.x - mu) * rs * g4.x + l4.x;
        a4.y = (h4.y - mu) * rs * g4.y + l4.y;
        a4.z = (h4.z - mu) * rs * g4.z + l4.z;
        a4.w = (h4.w - mu) * rs * g4.w + l4.w;
        __syncthreads();
        As[lkq * 4 + 0][lm] = a4.x;
        As[lkq * 4 + 1][lm] = a4.y;
        As[lkq * 4 + 2][lm] = a4.z;
        As[lkq * 4 + 3][lm] = a4.w;
        *(float4*)&Bs[lk][lnq * 4]      = b40;
        *(float4*)&Bs[lk][64 + lnq * 4] = b41;
        __syncthreads();
#pragma unroll
        for (int k = 0; k < KC; k++) {
            float4 a  = *(const float4*)&As[k][ty * 4];
            float4 bA = *(const float4*)&Bs[k][tx * 4];
            float4 bB = *(const float4*)&Bs[k][64 + tx * 4];
            unsigned long long q0 = pk2(bA.x, bA.y), q1 = pk2(bA.z, bA.w);
            unsigned long long q2 = pk2(bB.x, bB.y), q3 = pk2(bB.z, bB.w);
            float am[4] = {a.x, a.y, a.z, a.w};
#pragma unroll
            for (int mj = 0; mj < 4; mj++) {
                unsigned long long s = splat2(am[mj]);
                ffma2(c[mj][0], s, q0);
                ffma2(c[mj][1], s, q1);
                ffma2(c[mj][2], s, q2);
                ffma2(c[mj][3], s, q3);
            }
        }
    }
    float4 bb0 = *(const float4*)&b2[e * DIM + n0 + tx * 4];
    float4 bb1 = *(const float4*)&b2[e * DIM + n0 + 64 + tx * 4];
#pragma unroll
    for (int mj = 0; mj < 4; mj++) {
        int slot = s_slot[ty * 4 + mj];
        if (slot < 0) continue;
        float2 v0 = unpk2(c[mj][0]);
        float2 v1 = unpk2(c[mj][1]);
        float2 v2 = unpk2(c[mj][2]);
        float2 v3 = unpk2(c[mj][3]);
        float4 o0 = make_float4(v0.x + bb0.x, v0.y + bb0.y, v1.x + bb0.z, v1.y + bb0.w);
        float4 o1 = make_float4(v2.x + bb1.x, v2.y + bb1.y, v3.x + bb1.z, v3.y + bb1.w);
        float* yrow = g_ybuf + (size_t)slot * DIM + n0;
        *(float4*)&yrow[tx * 4]      = o0;
        *(float4*)&yrow[64 + tx * 4] = o1;
    }
}

// out[t][d] = w0*y[t,0][d] + w1*y[t,1][d]
__global__ __launch_bounds__(256) void combine_kernel(float* __restrict__ out) {
    int i = blockIdx.x * blockDim.x + threadIdx.x;    // over TOKENS*DIM/4
    if (i >= TOKENS * DIM / 4) return;
    int t  = i / (DIM / 4);
    int d4 = (i % (DIM / 4)) * 4;
    float w0 = g_wk[t * 2 + 0];
    float w1 = g_wk[t * 2 + 1];
    float4 y0 = *(const float4*)&g_ybuf[(size_t)(t * 2 + 0) * DIM + d4];
    float4 y1 = *(const float4*)&g_ybuf[(size_t)(t * 2 + 1) * DIM + d4];
    float4 o;
    o.x = w0 * y0.x + w1 * y1.x;
    o.y = w0 * y0.y + w1 * y1.y;
    o.z = w0 * y0.z + w1 * y1.z;
    o.w = w0 * y0.w + w1 * y1.w;
    *(float4*)&out[(size_t)t * DIM + d4] = o;
}

extern "C" void kernel_launch(void* const* d_in, const int* in_sizes, int n_in,
                              void* d_out, int out_size) {
    const float* x    = (const float*)d_in[0];
    const float* Wg   = (const float*)d_in[1];
    const float* W1   = (const float*)d_in[2];
    const float* b1   = (const float*)d_in[3];
    const float* ln_g = (const float*)d_in[4];
    const float* ln_b = (const float*)d_in[5];
    const float* W2   = (const float*)d_in[6];
    const float* b2   = (const float*)d_in[7];
    float* out = (float*)d_out;

    init_kernel<<<1, 32>>>();
    route_kernel<<<(TOKENS * 32 + 255) / 256, 256>>>(x, Wg);
    tilelist_kernel<<<1, 1>>>();
    gemm1_kernel<<<dim3(HID / TN, MAX_TILES), 256>>>(x, W1, b1);
    lnstats_kernel<<<NSLOTS, 256>>>();
    gemm2_kernel<<<dim3(DIM / TN, MAX_TILES), 256>>>(W2, b2, ln_g, ln_b);
    combine_kernel<<<(TOKENS * DIM / 4 + 255) / 256, 256>>>(out);
}

// round 3
// speedup vs baseline: 1.1900x; 1.1900x over previous
#include <cuda_runtime.h>
#include <cstdint>
#include <math.h>

#define TOKENS 2048
#define DIM    512
#define NEXP   16
#define HID    2048
#define NSLOTS (TOKENS*2)
#define TMT    128
#define KC     16
#define MAXT   48
#define NB1    (HID/128)   // 16
#define NB2    (DIM/128)   // 4

// ---------------- device scratch ----------------
__device__ int   g_cnt[NEXP];
__device__ int   g_list[NEXP*TOKENS];
__device__ float g_wk[NSLOTS];
__device__ int   g_perm[NSLOTS];
__device__ int   g_inv[NSLOTS];
__device__ int   g_te[MAXT], g_tg[MAXT], g_tr[MAXT];
__device__ int   g_ntiles;
__device__ float g_mu[NSLOTS], g_rs[NSLOTS];
__device__ float g_psum[NSLOTS*NB1], g_psq[NSLOTS*NB1];
__device__ float g_hbuf[(size_t)NSLOTS*HID];
__device__ float g_ybuf[(size_t)NSLOTS*DIM];

// ---------------- helpers ----------------
__device__ __forceinline__ uint32_t tf32r(float x) {
    uint32_t r; asm("cvt.rna.tf32.f32 %0, %1;" : "=r"(r) : "f"(x)); return r;
}
__device__ __forceinline__ void mma8(float* d, const uint32_t* a, const uint32_t* b) {
    asm volatile("mma.sync.aligned.m16n8k8.row.col.f32.tf32.tf32.f32 "
        "{%0,%1,%2,%3}, {%4,%5,%6,%7}, {%8,%9}, {%0,%1,%2,%3};"
        : "+f"(d[0]), "+f"(d[1]), "+f"(d[2]), "+f"(d[3])
        : "r"(a[0]), "r"(a[1]), "r"(a[2]), "r"(a[3]), "r"(b[0]), "r"(b[1]));
}
__device__ __forceinline__ float silu(float v) { return v / (1.f + __expf(-v)); }

// ---------------- small kernels ----------------
__global__ void init_kernel() {
    if (threadIdx.x < NEXP) g_cnt[threadIdx.x] = 0;
}

__global__ __launch_bounds__(256) void route_kernel(const float* __restrict__ x,
                                                    const float* __restrict__ Wg) {
    int t = (blockIdx.x * blockDim.x + threadIdx.x) >> 5;
    int lane = threadIdx.x & 31;
    if (t >= TOKENS) return;
    const float* xr = x + (size_t)t * DIM;
    float acc = 0.f;
    if (lane < NEXP) {
#pragma unroll 8
        for (int d = 0; d < DIM; d++) acc = fmaf(xr[d], Wg[d * NEXP + lane], acc);
    }
    float v0 = -1e30f, v1 = -1e30f;
    int i0 = 0, i1 = 0;
#pragma unroll
    for (int i = 0; i < NEXP; i++) {
        float vi = __shfl_sync(0xffffffffu, acc, i);
        if (vi > v0)      { v1 = v0; i1 = i0; v0 = vi; i0 = i; }
        else if (vi > v1) { v1 = vi; i1 = i; }
    }
    if (lane == 0) {
        float e1 = __expf(v1 - v0);
        float s  = 1.f + e1;
        g_wk[t * 2 + 0] = 1.f / s;
        g_wk[t * 2 + 1] = e1 / s;
        int p0 = atomicAdd(&g_cnt[i0], 1);
        g_list[i0 * TOKENS + p0] = t * 2 + 0;
        int p1 = atomicAdd(&g_cnt[i1], 1);
        g_list[i1 * TOKENS + p1] = t * 2 + 1;
    }
}

__global__ void pack_kernel() {
    __shared__ int off[NEXP];
    int tid = threadIdx.x;
    if (tid == 0) {
        int a = 0, nt = 0;
        for (int e = 0; e < NEXP; e++) {
            off[e] = a;
            int c = g_cnt[e];
            for (int m = 0; m < c; m += TMT) {
                g_te[nt] = e; g_tg[nt] = a + m;
                g_tr[nt] = (c - m < TMT) ? (c - m) : TMT;
                nt++;
            }
            a += c;
        }
        g_ntiles = nt;
    }
    __syncthreads();
    for (int e = 0; e < NEXP; e++) {
        int c = g_cnt[e], o = off[e];
        for (int i = tid; i < c; i += blockDim.x) {
            int sl = g_list[e * TOKENS + i];
            g_perm[o + i] = sl;
            g_inv[sl] = o + i;
        }
    }
}

// ---------------- GEMM1: h = silu(x @ W1 + b1), fused LN partials ----------------
__global__ __launch_bounds__(256) void gemm1_kernel(const float* __restrict__ x,
                                                    const float* __restrict__ W1,
                                                    const float* __restrict__ b1) {
    __shared__ uint32_t As[2][KC][136];
    __shared__ uint32_t Bs[2][KC][136];
    __shared__ int s_tok[TMT];
    __shared__ float s_sum[4][TMT], s_sq[4][TMT];
    int tile = blockIdx.y;
    if (tile >= g_ntiles) return;
    int e = g_te[tile], gp0 = g_tg[tile], rows = g_tr[tile];
    int n0 = blockIdx.x * 128;
    int tid = threadIdx.x, lane = tid & 31;
    int wid = tid >> 5;
    int g = lane >> 2, tg = lane & 3;
    int wm = wid & 1, wn = wid >> 1;
    if (tid < TMT) {
        int r = (tid < rows) ? tid : rows - 1;
        s_tok[tid] = g_perm[gp0 + r] >> 1;
    }
    __syncthreads();

    int lrow = tid & 127, c4a = tid >> 7;
    int bk = tid >> 5, bn4 = tid & 31;
    const float* aP = x + (size_t)s_tok[lrow] * DIM;
    const float* bP = W1 + (size_t)e * DIM * HID + n0 + bn4 * 4;

    float d[4][4][4];
#pragma unroll
    for (int i = 0; i < 4; i++)
#pragma unroll
        for (int j = 0; j < 4; j++)
#pragma unroll
            for (int c = 0; c < 4; c++) d[i][j][c] = 0.f;

    float4 av[2], bv[2];
#pragma unroll
    for (int i = 0; i < 2; i++) {
        av[i] = *(const float4*)(aP + (c4a + 2 * i) * 4);
        bv[i] = *(const float4*)(bP + (size_t)(bk + 8 * i) * HID);
    }
#pragma unroll
    for (int i = 0; i < 2; i++) {
        int c4 = c4a + 2 * i;
        As[0][c4 * 4 + 0][lrow] = tf32r(av[i].x);
        As[0][c4 * 4 + 1][lrow] = tf32r(av[i].y);
        As[0][c4 * 4 + 2][lrow] = tf32r(av[i].z);
        As[0][c4 * 4 + 3][lrow] = tf32r(av[i].w);
        int kk = bk + 8 * i;
        uint4 p = make_uint4(tf32r(bv[i].x), tf32r(bv[i].y), tf32r(bv[i].z), tf32r(bv[i].w));
        *(uint4*)&Bs[0][kk][bn4 * 4] = p;
    }
    __syncthreads();

    const int S = DIM / KC;   // 32
    for (int s = 0; s < S; s++) {
        int cur = s & 1;
        if (s + 1 < S) {
            int k0 = (s + 1) * KC;
#pragma unroll
            for (int i = 0; i < 2; i++) {
                av[i] = *(const float4*)(aP + k0 + (c4a + 2 * i) * 4);
                bv[i] = *(const float4*)(bP + (size_t)(k0 + bk + 8 * i) * HID);
            }
        }
#pragma unroll
        for (int k8 = 0; k8 < KC; k8 += 8) {
            uint32_t af[4][4], bf[4][2];
#pragma unroll
            for (int mf = 0; mf < 4; mf++) {
                int m = wm * 64 + mf * 16 + g;
                af[mf][0] = As[cur][k8 + tg][m];
                af[mf][1] = As[cur][k8 + tg][m + 8];
                af[mf][2] = As[cur][k8 + tg + 4][m];
                af[mf][3] = As[cur][k8 + tg + 4][m + 8];
            }
#pragma unroll
            for (int nf = 0; nf < 4; nf++) {
                int n = wn * 32 + nf * 8 + g;
                bf[nf][0] = Bs[cur][k8 + tg][n];
                bf[nf][1] = Bs[cur][k8 + tg + 4][n];
            }
#pragma unroll
            for (int mf = 0; mf < 4; mf++)
#pragma unroll
                for (int nf = 0; nf < 4; nf++)
                    mma8(d[mf][nf], af[mf], bf[nf]);
        }
        __syncthreads();
        if (s + 1 < S) {
            int nx = (s + 1) & 1;
#pragma unroll
            for (int i = 0; i < 2; i++) {
                int c4 = c4a + 2 * i;
                As[nx][c4 * 4 + 0][lrow] = tf32r(av[i].x);
                As[nx][c4 * 4 + 1][lrow] = tf32r(av[i].y);
                As[nx][c4 * 4 + 2][lrow] = tf32r(av[i].z);
                As[nx][c4 * 4 + 3][lrow] = tf32r(av[i].w);
                int kk = bk + 8 * i;
                uint4 p = make_uint4(tf32r(bv[i].x), tf32r(bv[i].y), tf32r(bv[i].z), tf32r(bv[i].w));
                *(uint4*)&Bs[nx][kk][bn4 * 4] = p;
            }
            __syncthreads();
        }
    }

    // epilogue: bias + silu + store hbuf + per-row LN partials
    const float* brow = b1 + (size_t)e * HID + n0;
    float bias[4][2];
#pragma unroll
    for (int nf = 0; nf < 4; nf++) {
        int n = wn * 32 + nf * 8 + tg * 2;
        bias[nf][0] = brow[n];
        bias[nf][1] = brow[n + 1];
    }
#pragma unroll
    for (int mf = 0; mf < 4; mf++) {
#pragma unroll
        for (int h = 0; h < 2; h++) {
            int lr = wm * 64 + mf * 16 + g + 8 * h;
            bool val = (lr < rows);
            int gp = gp0 + lr;
            float ss = 0.f, qq = 0.f;
            float* hrow = g_hbuf + (size_t)gp * HID + n0;
#pragma unroll
            for (int nf = 0; nf < 4; nf++) {
                float v0 = silu(d[mf][nf][2 * h + 0] + bias[nf][0]);
                float v1 = silu(d[mf][nf][2 * h + 1] + bias[nf][1]);
                ss += v0 + v1;
                qq += v0 * v0 + v1 * v1;
                if (val) {
                    float2 o = make_float2(v0, v1);
                    *(float2*)(hrow + wn * 32 + nf * 8 + tg * 2) = o;
                }
            }
            ss += __shfl_xor_sync(0xffffffffu, ss, 1);
            ss += __shfl_xor_sync(0xffffffffu, ss, 2);
            qq += __shfl_xor_sync(0xffffffffu, qq, 1);
            qq += __shfl_xor_sync(0xffffffffu, qq, 2);
            if (tg == 0) { s_sum[wn][lr] = ss; s_sq[wn][lr] = qq; }
        }
    }
    __syncthreads();
    if (tid < TMT && tid < rows) {
        float ts = s_sum[0][tid] + s_sum[1][tid] + s_sum[2][tid] + s_sum[3][tid];
        float tq = s_sq[0][tid] + s_sq[1][tid] + s_sq[2][tid] + s_sq[3][tid];
        g_psum[(size_t)(gp0 + tid) * NB1 + blockIdx.x] = ts;
        g_psq [(size_t)(gp0 + tid) * NB1 + blockIdx.x] = tq;
    }
}

__global__ __launch_bounds__(256) void lnstats_kernel() {
    int w = (blockIdx.x * blockDim.x + threadIdx.x) >> 5;
    int lane = threadIdx.x & 31;
    if (w >= NSLOTS) return;
    float s = (lane < NB1) ? g_psum[(size_t)w * NB1 + lane] : 0.f;
    float q = (lane < NB1) ? g_psq [(size_t)w * NB1 + lane] : 0.f;
#pragma unroll
    for (int o = 8; o; o >>= 1) {
        s += __shfl_xor_sync(0xffffffffu, s, o);
        q += __shfl_xor_sync(0xffffffffu, q, o);
    }
    if (lane == 0) {
        float mu = s * (1.f / HID);
        float var = q * (1.f / HID) - mu * mu;
        g_mu[w] = mu;
        g_rs[w] = rsqrtf(var + 1e-5f);
    }
}

// ---------------- GEMM2: y = (LN(h)*g+b) @ W2 + b2, × gate weight ----------------
__global__ __launch_bounds__(256) void gemm2_kernel(const float* __restrict__ W2,
                                                    const float* __restrict__ b2,
                                                    const float* __restrict__ ln_g,
                                                    const float* __restrict__ ln_b) {
    __shared__ uint32_t As[2][KC][136];
    __shared__ uint32_t Bs[2][KC][136];
    __shared__ float s_w[TMT];
    int tile = blockIdx.y;
    if (tile >= g_ntiles) return;
    int e = g_te[tile], gp0 = g_tg[tile], rows = g_tr[tile];
    int n0 = blockIdx.x * 128;
    int tid = threadIdx.x, lane = tid & 31;
    int wid = tid >> 5;
    int g = lane >> 2, tg = lane & 3;
    int wm = wid & 1, wn = wid >> 1;
    if (tid < TMT)
        s_w[tid] = (tid < rows) ? g_wk[g_perm[gp0 + tid]] : 0.f;

    int lrow = tid & 127, c4a = tid >> 7;
    int bk = tid >> 5, bn4 = tid & 31;
    int arow = (lrow < rows) ? lrow : rows - 1;
    int agp = gp0 + arow;
    const float* aP = g_hbuf + (size_t)agp * HID;
    float mu = g_mu[agp], rs = g_rs[agp];
    const float* lg = ln_g + (size_t)e * HID;
    const float* lb = ln_b + (size_t)e * HID;
    const float* bP = W2 + (size_t)e * HID * DIM + n0 + bn4 * 4;

    float d[4][4][4];
#pragma unroll
    for (int i = 0; i < 4; i++)
#pragma unroll
        for (int j = 0; j < 4; j++)
#pragma unroll
            for (int c = 0; c < 4; c++) d[i][j][c] = 0.f;

    float4 av[2], gv[2], lv[2], bv[2];
#pragma unroll
    for (int i = 0; i < 2; i++) {
        int c4 = c4a + 2 * i;
        av[i] = *(const float4*)(aP + c4 * 4);
        gv[i] = *(const float4*)(lg + c4 * 4);
        lv[i] = *(const float4*)(lb + c4 * 4);
        bv[i] = *(const float4*)(bP + (size_t)(bk + 8 * i) * DIM);
    }
    __syncthreads();   // covers s_w too
#pragma unroll
    for (int i = 0; i < 2; i++) {
        int c4 = c4a + 2 * i;
        As[0][c4 * 4 + 0][lrow] = tf32r((av[i].x - mu) * rs * gv[i].x + lv[i].x);
        As[0][c4 * 4 + 1][lrow] = tf32r((av[i].y - mu) * rs * gv[i].y + lv[i].y);
        As[0][c4 * 4 + 2][lrow] = tf32r((av[i].z - mu) * rs * gv[i].z + lv[i].z);
        As[0][c4 * 4 + 3][lrow] = tf32r((av[i].w - mu) * rs * gv[i].w + lv[i].w);
        int kk = bk + 8 * i;
        uint4 p = make_uint4(tf32r(bv[i].x), tf32r(bv[i].y), tf32r(bv[i].z), tf32r(bv[i].w));
        *(uint4*)&Bs[0][kk][bn4 * 4] = p;
    }
    __syncthreads();

    const int S = HID / KC;   // 128
    for (int s = 0; s < S; s++) {
        int cur = s & 1;
        if (s + 1 < S) {
            int k0 = (s + 1) * KC;
#pragma unroll
            for (int i = 0; i < 2; i++) {
                int c4 = c4a + 2 * i;
                av[i] = *(const float4*)(aP + k0 + c4 * 4);
                gv[i] = *(const float4*)(lg + k0 + c4 * 4);
                lv[i] = *(const float4*)(lb + k0 + c4 * 4);
                bv[i] = *(const float4*)(bP + (size_t)(k0 + bk + 8 * i) * DIM);
            }
        }
#pragma unroll
        for (int k8 = 0; k8 < KC; k8 += 8) {
            uint32_t af[4][4], bf[4][2];
#pragma unroll
            for (int mf = 0; mf < 4; mf++) {
                int m = wm * 64 + mf * 16 + g;
                af[mf][0] = As[cur][k8 + tg][m];
                af[mf][1] = As[cur][k8 + tg][m + 8];
                af[mf][2] = As[cur][k8 + tg + 4][m];
                af[mf][3] = As[cur][k8 + tg + 4][m + 8];
            }
#pragma unroll
            for (int nf = 0; nf < 4; nf++) {
                int n = wn * 32 + nf * 8 + g;
                bf[nf][0] = Bs[cur][k8 + tg][n];
                bf[nf][1] = Bs[cur][k8 + tg + 4][n];
            }
#pragma unroll
            for (int mf = 0; mf < 4; mf++)
#pragma unroll
                for (int nf = 0; nf < 4; nf++)
                    mma8(d[mf][nf], af[mf], bf[nf]);
        }
        __syncthreads();
        if (s + 1 < S) {
            int nx = (s + 1) & 1;
#pragma unroll
            for (int i = 0; i < 2; i++) {
                int c4 = c4a + 2 * i;
                As[nx][c4 * 4 + 0][lrow] = tf32r((av[i].x - mu) * rs * gv[i].x + lv[i].x);
                As[nx][c4 * 4 + 1][lrow] = tf32r((av[i].y - mu) * rs * gv[i].y + lv[i].y);
                As[nx][c4 * 4 + 2][lrow] = tf32r((av[i].z - mu) * rs * gv[i].z + lv[i].z);
                As[nx][c4 * 4 + 3][lrow] = tf32r((av[i].w - mu) * rs * gv[i].w + lv[i].w);
                int kk = bk + 8 * i;
                uint4 p = make_uint4(tf32r(bv[i].x), tf32r(bv[i].y), tf32r(bv[i].z), tf32r(bv[i].w));
                *(uint4*)&Bs[nx][kk][bn4 * 4] = p;
            }
            __syncthreads();
        }
    }

    const float* brow = b2 + (size_t)e * DIM + n0;
    float bias[4][2];
#pragma unroll
    for (int nf = 0; nf < 4; nf++) {
        int n = wn * 32 + nf * 8 + tg * 2;
        bias[nf][0] = brow[n];
        bias[nf][1] = brow[n + 1];
    }
#pragma unroll
    for (int mf = 0; mf < 4; mf++) {
#pragma unroll
        for (int h = 0; h < 2; h++) {
            int lr = wm * 64 + mf * 16 + g + 8 * h;
            if (lr >= rows) continue;
            int gp = gp0 + lr;
            float w = s_w[lr];
            float* yrow = g_ybuf + (size_t)gp * DIM + n0;
#pragma unroll
            for (int nf = 0; nf < 4; nf++) {
                float v0 = (d[mf][nf][2 * h + 0] + bias[nf][0]) * w;
                float v1 = (d[mf][nf][2 * h + 1] + bias[nf][1]) * w;
                float2 o = make_float2(v0, v1);
                *(float2*)(yrow + wn * 32 + nf * 8 + tg * 2) = o;
            }
        }
    }
}

__global__ __launch_bounds__(256) void combine_kernel(float* __restrict__ out) {
    int i = blockIdx.x * 256 + threadIdx.x;
    int t = i >> 7;
    int d4 = (i & 127) * 4;
    int p0 = g_inv[t * 2 + 0];
    int p1 = g_inv[t * 2 + 1];
    float4 a = *(const float4*)&g_ybuf[(size_t)p0 * DIM + d4];
    float4 b = *(const float4*)&g_ybuf[(size_t)p1 * DIM + d4];
    float4 o = make_float4(a.x + b.x, a.y + b.y, a.z + b.z, a.w + b.w);
    *(float4*)&out[(size_t)t * DIM + d4] = o;
}

extern "C" void kernel_launch(void* const* d_in, const int* in_sizes, int n_in,
                              void* d_out, int out_size) {
    const float* x    = (const float*)d_in[0];
    const float* Wg   = (const float*)d_in[1];
    const float* W1   = (const float*)d_in[2];
    const float* b1   = (const float*)d_in[3];
    const float* ln_g = (const float*)d_in[4];
    const float* ln_b = (const float*)d_in[5];
    const float* W2   = (const float*)d_in[6];
    const float* b2   = (const float*)d_in[7];
    float* out = (float*)d_out;

    init_kernel<<<1, 32>>>();
    route_kernel<<<(TOKENS * 32 + 255) / 256, 256>>>(x, Wg);
    pack_kernel<<<1, 256>>>();
    gemm1_kernel<<<dim3(NB1, MAXT), 256>>>(x, W1, b1);
    lnstats_kernel<<<NSLOTS * 32 / 256, 256>>>();
    gemm2_kernel<<<dim3(NB2, MAXT), 256>>>(W2, b2, ln_g, ln_b);
    combine_kernel<<<TOKENS * DIM / 4 / 256, 256>>>(out);
}

// round 4
// speedup vs baseline: 1.7892x; 1.5036x over previous
#include <cuda_runtime.h>
#include <cstdint>
#include <math.h>

#define TOKENS 2048
#define DIM    512
#define NEXP   16
#define HID    2048
#define NSLOTS (TOKENS*2)
#define TMT    128
#define KC     32
#define MAXT   48
#define NB1    (HID/128)   // 16
#define NB2    (DIM/128)   // 4
#define ASTR   36          // A smem row stride (floats)
#define BSTR   136         // B smem row stride (floats)
#define ABYTES (128*ASTR*4)            // 18432
#define SBYTES (ABYTES + KC*BSTR*4)    // 35840
#define SFLOAT (SBYTES/4)
#define AFLOAT (ABYTES/4)

// ---------------- device scratch ----------------
__device__ int   g_cnt[NEXP];
__device__ int   g_list[NEXP*TOKENS];
__device__ float g_wk[NSLOTS];
__device__ int   g_perm[NSLOTS];
__device__ int   g_inv[NSLOTS];
__device__ int   g_rowe[NSLOTS];
__device__ int   g_te[MAXT], g_tg[MAXT], g_tr[MAXT];
__device__ int   g_ntiles;
__device__ float g_psum[NSLOTS*NB1], g_psq[NSLOTS*NB1];
__device__ float g_xr[(size_t)TOKENS*DIM];
__device__ float g_hbuf[(size_t)NSLOTS*HID];
__device__ float g_ybuf[(size_t)NSLOTS*DIM];

// ---------------- helpers ----------------
__device__ __forceinline__ uint32_t smem_u32(const void* p) {
    uint32_t a;
    asm("{ .reg .u64 t; cvta.to.shared.u64 t, %1; cvt.u32.u64 %0, t; }" : "=r"(a) : "l"(p));
    return a;
}
__device__ __forceinline__ uint32_t tf32r(float x) {
    uint32_t r; asm("cvt.rna.tf32.f32 %0, %1;" : "=r"(r) : "f"(x)); return r;
}
__device__ __forceinline__ float tf32f(float x) { return __uint_as_float(tf32r(x)); }
__device__ __forceinline__ void mma8(float* d, const uint32_t* a, const uint32_t* b) {
    asm volatile("mma.sync.aligned.m16n8k8.row.col.f32.tf32.tf32.f32 "
        "{%0,%1,%2,%3}, {%4,%5,%6,%7}, {%8,%9}, {%0,%1,%2,%3};"
        : "+f"(d[0]), "+f"(d[1]), "+f"(d[2]), "+f"(d[3])
        : "r"(a[0]), "r"(a[1]), "r"(a[2]), "r"(a[3]), "r"(b[0]), "r"(b[1]));
}
__device__ __forceinline__ void cpa16(uint32_t dst, const float* src) {
    asm volatile("cp.async.cg.shared.global [%0], [%1], 16;" :: "r"(dst), "l"(src));
}
#define CP_COMMIT() asm volatile("cp.async.commit_group;" ::: "memory")
#define CP_WAIT1()  asm volatile("cp.async.wait_group 1;" ::: "memory")
__device__ __forceinline__ float silu(float v) { return v / (1.f + __expf(-v)); }

// ---------------- small kernels ----------------
__global__ void init_kernel() {
    if (threadIdx.x < NEXP) g_cnt[threadIdx.x] = 0;
}

__global__ __launch_bounds__(256) void xcvt_kernel(const float* __restrict__ x) {
    int i = blockIdx.x * 256 + threadIdx.x;   // over TOKENS*DIM/4
    float4 v = ((const float4*)x)[i];
    v.x = tf32f(v.x); v.y = tf32f(v.y); v.z = tf32f(v.z); v.w = tf32f(v.w);
    ((float4*)g_xr)[i] = v;
}

__global__ __launch_bounds__(256) void route_kernel(const float* __restrict__ x,
                                                    const float* __restrict__ Wg) {
    int t = (blockIdx.x * blockDim.x + threadIdx.x) >> 5;
    int lane = threadIdx.x & 31;
    if (t >= TOKENS) return;
    const float* xr = x + (size_t)t * DIM;
    float acc = 0.f;
    if (lane < NEXP) {
#pragma unroll 8
        for (int d = 0; d < DIM; d++) acc = fmaf(xr[d], Wg[d * NEXP + lane], acc);
    }
    float v0 = -1e30f, v1 = -1e30f;
    int i0 = 0, i1 = 0;
#pragma unroll
    for (int i = 0; i < NEXP; i++) {
        float vi = __shfl_sync(0xffffffffu, acc, i);
        if (vi > v0)      { v1 = v0; i1 = i0; v0 = vi; i0 = i; }
        else if (vi > v1) { v1 = vi; i1 = i; }
    }
    if (lane == 0) {
        float e1 = __expf(v1 - v0);
        float s  = 1.f + e1;
        g_wk[t * 2 + 0] = 1.f / s;
        g_wk[t * 2 + 1] = e1 / s;
        int p0 = atomicAdd(&g_cnt[i0], 1);
        g_list[i0 * TOKENS + p0] = t * 2 + 0;
        int p1 = atomicAdd(&g_cnt[i1], 1);
        g_list[i1 * TOKENS + p1] = t * 2 + 1;
    }
}

__global__ void pack_kernel() {
    __shared__ int off[NEXP];
    int tid = threadIdx.x;
    if (tid == 0) {
        int a = 0, nt = 0;
        for (int e = 0; e < NEXP; e++) {
            off[e] = a;
            int c = g_cnt[e];
            for (int m = 0; m < c; m += TMT) {
                g_te[nt] = e; g_tg[nt] = a + m;
                g_tr[nt] = (c - m < TMT) ? (c - m) : TMT;
                nt++;
            }
            a += c;
        }
        g_ntiles = nt;
    }
    __syncthreads();
    for (int e = 0; e < NEXP; e++) {
        int c = g_cnt[e], o = off[e];
        for (int i = tid; i < c; i += blockDim.x) {
            int sl = g_list[e * TOKENS + i];
            g_perm[o + i] = sl;
            g_inv[sl] = o + i;
            g_rowe[o + i] = e;
        }
    }
}

// ---------------- GEMM1: h = silu(xr @ W1 + b1), fused LN partials ----------------
__global__ __launch_bounds__(256, 2) void gemm1_kernel(const float* __restrict__ W1,
                                                       const float* __restrict__ b1) {
    extern __shared__ float dsm[];
    __shared__ int s_tok[TMT];
    int tile = blockIdx.y;
    if (tile >= g_ntiles) return;
    int e = g_te[tile], gp0 = g_tg[tile], rows = g_tr[tile];
    int n0 = blockIdx.x * 128;
    int tid = threadIdx.x, lane = tid & 31, wid = tid >> 5;
    int g = lane >> 2, tg = lane & 3;
    int wm = wid & 1, wn = wid >> 1;
    uint32_t dynb = smem_u32(dsm);

    if (tid < TMT) {
        int r = (tid < rows) ? tid : rows - 1;
        s_tok[tid] = g_perm[gp0 + r] >> 1;
    }
    __syncthreads();

    // precomputed load maps (4 A chunks + 4 B chunks per thread per stage)
    const float* pA[4]; uint32_t dA[4];
    const float* pB[4]; uint32_t dB[4];
    const float* Wb = W1 + (size_t)e * DIM * HID + n0;
#pragma unroll
    for (int i = 0; i < 4; i++) {
        int c = tid + 256 * i;
        int row = c >> 3, fo = (c & 7) * 4;
        pA[i] = g_xr + (size_t)s_tok[row] * DIM + fo;
        dA[i] = dynb + (uint32_t)(row * (ASTR * 4) + fo * 4);
        int kr = c >> 5, nc = (c & 31) * 4;
        pB[i] = Wb + (size_t)kr * HID + nc;
        dB[i] = dynb + (uint32_t)(ABYTES + kr * (BSTR * 4) + nc * 4);
    }

    float d[4][4][4];
#pragma unroll
    for (int i = 0; i < 4; i++)
#pragma unroll
        for (int j = 0; j < 4; j++)
#pragma unroll
            for (int c = 0; c < 4; c++) d[i][j][c] = 0.f;

    const int S = DIM / KC;   // 16
    // prologue: stages 0,1
#pragma unroll
    for (int ps = 0; ps < 2; ps++) {
#pragma unroll
        for (int i = 0; i < 4; i++) {
            cpa16(dA[i] + ps * SBYTES, pA[i] + ps * KC);
            cpa16(dB[i] + ps * SBYTES, pB[i] + (size_t)ps * KC * HID);
        }
        CP_COMMIT();
    }

    int st = 0, si = 2;
    for (int s = 0; s < S; s++) {
        CP_WAIT1();
        __syncthreads();
        if (s + 2 < S) {
            int k0 = (s + 2) * KC;
#pragma unroll
            for (int i = 0; i < 4; i++) {
                cpa16(dA[i] + si * SBYTES, pA[i] + k0);
                cpa16(dB[i] + si * SBYTES, pB[i] + (size_t)k0 * HID);
            }
        }
        CP_COMMIT();
        const float* Ab = dsm + st * SFLOAT;
        const float* Bb = Ab + AFLOAT;
#pragma unroll
        for (int k8 = 0; k8 < KC; k8 += 8) {
            uint32_t af[4][4], bf[4][2];
#pragma unroll
            for (int mf = 0; mf < 4; mf++) {
                const float* ap = Ab + (wm * 64 + mf * 16 + g) * ASTR + k8 + tg;
                af[mf][0] = __float_as_uint(ap[0]);
                af[mf][1] = __float_as_uint(ap[8 * ASTR]);
                af[mf][2] = __float_as_uint(ap[4]);
                af[mf][3] = __float_as_uint(ap[8 * ASTR + 4]);
            }
#pragma unroll
            for (int nf = 0; nf < 4; nf++) {
                const float* bp = Bb + (k8 + tg) * BSTR + wn * 32 + nf * 8 + g;
                bf[nf][0] = tf32r(bp[0]);
                bf[nf][1] = tf32r(bp[4 * BSTR]);
            }
#pragma unroll
            for (int mf = 0; mf < 4; mf++)
#pragma unroll
                for (int nf = 0; nf < 4; nf++)
                    mma8(d[mf][nf], af[mf], bf[nf]);
        }
        st = (st == 2) ? 0 : st + 1;
        si = (si == 2) ? 0 : si + 1;
    }
    __syncthreads();   // stage buffers now dead; alias for reductions
    float* s_sum = dsm;          // [4][128]
    float* s_sq  = dsm + 512;    // [4][128]

    const float* brow = b1 + (size_t)e * HID + n0;
    float bias[4][2];
#pragma unroll
    for (int nf = 0; nf < 4; nf++) {
        int n = wn * 32 + nf * 8 + tg * 2;
        bias[nf][0] = brow[n];
        bias[nf][1] = brow[n + 1];
    }
#pragma unroll
    for (int mf = 0; mf < 4; mf++) {
#pragma unroll
        for (int h = 0; h < 2; h++) {
            int lr = wm * 64 + mf * 16 + g + 8 * h;
            bool val = (lr < rows);
            int gp = gp0 + lr;
            float ss = 0.f, qq = 0.f;
            float* hrow = g_hbuf + (size_t)gp * HID + n0;
#pragma unroll
            for (int nf = 0; nf < 4; nf++) {
                float v0 = silu(d[mf][nf][2 * h + 0] + bias[nf][0]);
                float v1 = silu(d[mf][nf][2 * h + 1] + bias[nf][1]);
                ss += v0 + v1;
                qq += v0 * v0 + v1 * v1;
                if (val) {
                    float2 o = make_float2(v0, v1);
                    *(float2*)(hrow + wn * 32 + nf * 8 + tg * 2) = o;
                }
            }
            ss += __shfl_xor_sync(0xffffffffu, ss, 1);
            ss += __shfl_xor_sync(0xffffffffu, ss, 2);
            qq += __shfl_xor_sync(0xffffffffu, qq, 1);
            qq += __shfl_xor_sync(0xffffffffu, qq, 2);
            if (tg == 0) { s_sum[wn * TMT + lr] = ss; s_sq[wn * TMT + lr] = qq; }
        }
    }
    __syncthreads();
    if (tid < TMT && tid < rows) {
        float ts = s_sum[tid] + s_sum[TMT + tid] + s_sum[2 * TMT + tid] + s_sum[3 * TMT + tid];
        float tq = s_sq[tid] + s_sq[TMT + tid] + s_sq[2 * TMT + tid] + s_sq[3 * TMT + tid];
        g_psum[(size_t)(gp0 + tid) * NB1 + blockIdx.x] = ts;
        g_psq [(size_t)(gp0 + tid) * NB1 + blockIdx.x] = tq;
    }
}

// ---------------- lnfix: stats reduce + LN transform + tf32 round, in place ----------------
__global__ __launch_bounds__(256) void lnfix_kernel(const float* __restrict__ ln_g,
                                                    const float* __restrict__ ln_b) {
    __shared__ float smu, srs;
    int gp = blockIdx.x;
    int tid = threadIdx.x;
    int e = g_rowe[gp];
    if (tid < 32) {
        float s = (tid < NB1) ? g_psum[(size_t)gp * NB1 + tid] : 0.f;
        float q = (tid < NB1) ? g_psq [(size_t)gp * NB1 + tid] : 0.f;
#pragma unroll
        for (int o = 8; o; o >>= 1) {
            s += __shfl_xor_sync(0xffffffffu, s, o);
            q += __shfl_xor_sync(0xffffffffu, q, o);
        }
        if (tid == 0) {
            float mu = s * (1.f / HID);
            float var = q * (1.f / HID) - mu * mu;
            smu = mu;
            srs = rsqrtf(var + 1e-5f);
        }
    }
    __syncthreads();
    float mu = smu, rs = srs;
    float4* h = (float4*)(g_hbuf + (size_t)gp * HID);
    const float4* gg = (const float4*)(ln_g + (size_t)e * HID);
    const float4* bb = (const float4*)(ln_b + (size_t)e * HID);
#pragma unroll
    for (int i = 0; i < 2; i++) {
        int idx = tid + i * 256;
        float4 v = h[idx], G = gg[idx], B = bb[idx];
        v.x = tf32f((v.x - mu) * rs * G.x + B.x);
        v.y = tf32f((v.y - mu) * rs * G.y + B.y);
        v.z = tf32f((v.z - mu) * rs * G.z + B.z);
        v.w = tf32f((v.w - mu) * rs * G.w + B.w);
        h[idx] = v;
    }
}

// ---------------- GEMM2: y = hfix @ W2 + b2, × gate weight ----------------
__global__ __launch_bounds__(256, 2) void gemm2_kernel(const float* __restrict__ W2,
                                                       const float* __restrict__ b2) {
    extern __shared__ float dsm[];
    __shared__ int s_gp[TMT];
    __shared__ float s_w[TMT];
    int tile = blockIdx.y;
    if (tile >= g_ntiles) return;
    int e = g_te[tile], gp0 = g_tg[tile], rows = g_tr[tile];
    int n0 = blockIdx.x * 128;
    int tid = threadIdx.x, lane = tid & 31, wid = tid >> 5;
    int g = lane >> 2, tg = lane & 3;
    int wm = wid & 1, wn = wid >> 1;
    uint32_t dynb = smem_u32(dsm);

    if (tid < TMT) {
        int r = (tid < rows) ? tid : rows - 1;
        s_gp[tid] = gp0 + r;
        s_w[tid] = (tid < rows) ? g_wk[g_perm[gp0 + tid]] : 0.f;
    }
    __syncthreads();

    const float* pA[4]; uint32_t dA[4];
    const float* pB[4]; uint32_t dB[4];
    const float* Wb = W2 + (size_t)e * HID * DIM + n0;
#pragma unroll
    for (int i = 0; i < 4; i++) {
        int c = tid + 256 * i;
        int row = c >> 3, fo = (c & 7) * 4;
        pA[i] = g_hbuf + (size_t)s_gp[row] * HID + fo;
        dA[i] = dynb + (uint32_t)(row * (ASTR * 4) + fo * 4);
        int kr = c >> 5, nc = (c & 31) * 4;
        pB[i] = Wb + (size_t)kr * DIM + nc;
        dB[i] = dynb + (uint32_t)(ABYTES + kr * (BSTR * 4) + nc * 4);
    }

    float d[4][4][4];
#pragma unroll
    for (int i = 0; i < 4; i++)
#pragma unroll
        for (int j = 0; j < 4; j++)
#pragma unroll
            for (int c = 0; c < 4; c++) d[i][j][c] = 0.f;

    const int S = HID / KC;   // 64
#pragma unroll
    for (int ps = 0; ps < 2; ps++) {
#pragma unroll
        for (int i = 0; i < 4; i++) {
            cpa16(dA[i] + ps * SBYTES, pA[i] + ps * KC);
            cpa16(dB[i] + ps * SBYTES, pB[i] + (size_t)ps * KC * DIM);
        }
        CP_COMMIT();
    }

    int st = 0, si = 2;
    for (int s = 0; s < S; s++) {
        CP_WAIT1();
        __syncthreads();
        if (s + 2 < S) {
            int k0 = (s + 2) * KC;
#pragma unroll
            for (int i = 0; i < 4; i++) {
                cpa16(dA[i] + si * SBYTES, pA[i] + k0);
                cpa16(dB[i] + si * SBYTES, pB[i] + (size_t)k0 * DIM);
            }
        }
        CP_COMMIT();
        const float* Ab = dsm + st * SFLOAT;
        const float* Bb = Ab + AFLOAT;
#pragma unroll
        for (int k8 = 0; k8 < KC; k8 += 8) {
            uint32_t af[4][4], bf[4][2];
#pragma unroll
            for (int mf = 0; mf < 4; mf++) {
                const float* ap = Ab + (wm * 64 + mf * 16 + g) * ASTR + k8 + tg;
                af[mf][0] = __float_as_uint(ap[0]);
                af[mf][1] = __float_as_uint(ap[8 * ASTR]);
                af[mf][2] = __float_as_uint(ap[4]);
                af[mf][3] = __float_as_uint(ap[8 * ASTR + 4]);
            }
#pragma unroll
            for (int nf = 0; nf < 4; nf++) {
                const float* bp = Bb + (k8 + tg) * BSTR + wn * 32 + nf * 8 + g;
                bf[nf][0] = tf32r(bp[0]);
                bf[nf][1] = tf32r(bp[4 * BSTR]);
            }
#pragma unroll
            for (int mf = 0; mf < 4; mf++)
#pragma unroll
                for (int nf = 0; nf < 4; nf++)
                    mma8(d[mf][nf], af[mf], bf[nf]);
        }
        st = (st == 2) ? 0 : st + 1;
        si = (si == 2) ? 0 : si + 1;
    }

    const float* brow = b2 + (size_t)e * DIM + n0;
    float bias[4][2];
#pragma unroll
    for (int nf = 0; nf < 4; nf++) {
        int n = wn * 32 + nf * 8 + tg * 2;
        bias[nf][0] = brow[n];
        bias[nf][1] = brow[n + 1];
    }
#pragma unroll
    for (int mf = 0; mf < 4; mf++) {
#pragma unroll
        for (int h = 0; h < 2; h++) {
            int lr = wm * 64 + mf * 16 + g + 8 * h;
            if (lr >= rows) continue;
            int gp = gp0 + lr;
            float w = s_w[lr];
            float* yrow = g_ybuf + (size_t)gp * DIM + n0;
#pragma unroll
            for (int nf = 0; nf < 4; nf++) {
                float v0 = (d[mf][nf][2 * h + 0] + bias[nf][0]) * w;
                float v1 = (d[mf][nf][2 * h + 1] + bias[nf][1]) * w;
                *(float2*)(yrow + wn * 32 + nf * 8 + tg * 2) = make_float2(v0, v1);
            }
        }
    }
}

__global__ __launch_bounds__(256) void combine_kernel(float* __restrict__ out) {
    int i = blockIdx.x * 256 + threadIdx.x;
    int t = i >> 7;
    int d4 = (i & 127) * 4;
    int p0 = g_inv[t * 2 + 0];
    int p1 = g_inv[t * 2 + 1];
    float4 a = *(const float4*)&g_ybuf[(size_t)p0 * DIM + d4];
    float4 b = *(const float4*)&g_ybuf[(size_t)p1 * DIM + d4];
    *(float4*)&out[(size_t)t * DIM + d4] =
        make_float4(a.x + b.x, a.y + b.y, a.z + b.z, a.w + b.w);
}

extern "C" void kernel_launch(void* const* d_in, const int* in_sizes, int n_in,
                              void* d_out, int out_size) {
    const float* x    = (const float*)d_in[0];
    const float* Wg   = (const float*)d_in[1];
    const float* W1   = (const float*)d_in[2];
    const float* b1   = (const float*)d_in[3];
    const float* ln_g = (const float*)d_in[4];
    const float* ln_b = (const float*)d_in[5];
    const float* W2   = (const float*)d_in[6];
    const float* b2   = (const float*)d_in[7];
    float* out = (float*)d_out;

    static int configured = 0;
    cudaFuncSetAttribute(gemm1_kernel, cudaFuncAttributeMaxDynamicSharedMemorySize, 3 * SBYTES);
    cudaFuncSetAttribute(gemm2_kernel, cudaFuncAttributeMaxDynamicSharedMemorySize, 3 * SBYTES);
    (void)configured;

    init_kernel<<<1, 32>>>();
    xcvt_kernel<<<TOKENS * DIM / 4 / 256, 256>>>(x);
    route_kernel<<<(TOKENS * 32 + 255) / 256, 256>>>(x, Wg);
    pack_kernel<<<1, 256>>>();
    gemm1_kernel<<<dim3(NB1, MAXT), 256, 3 * SBYTES>>>(W1, b1);
    lnfix_kernel<<<NSLOTS, 256>>>(ln_g, ln_b);
    gemm2_kernel<<<dim3(NB2, MAXT), 256, 3 * SBYTES>>>(W2, b2);
    combine_kernel<<<TOKENS * DIM / 4 / 256, 256>>>(out);
}

// round 5
// speedup vs baseline: 1.8068x; 1.0098x over previous
#include <cuda_runtime.h>
#include <cstdint>
#include <math.h>

#define TOKENS 2048
#define DIM    512
#define NEXP   16
#define HID    2048
#define NSLOTS (TOKENS*2)
#define TMT    128
#define KC     32
#define MAXT   48
#define NB1    (HID/128)   // 16
#define NB2    (DIM/128)   // 4
#define ASTR   40          // A smem row stride (floats) — conflict-free for LDS.64 pattern
#define BSTR   136         // B smem row stride (floats)
#define ABYTES (128*ASTR*4)            // 20480
#define SBYTES (ABYTES + KC*BSTR*4)    // 37888
#define SFLOAT (SBYTES/4)
#define AFLOAT (ABYTES/4)

// ---------------- device scratch ----------------
__device__ int   g_cnt[NEXP];
__device__ int   g_off[NEXP];
__device__ int   g_list[NEXP*TOKENS];
__device__ float g_wk[NSLOTS];
__device__ int   g_perm[NSLOTS];
__device__ int   g_inv[NSLOTS];
__device__ int   g_rowe[NSLOTS];
__device__ int   g_te[MAXT], g_tg[MAXT], g_tr[MAXT];
__device__ int   g_ntiles;
__device__ float g_psum[NSLOTS*NB1], g_psq[NSLOTS*NB1];
__device__ float g_xr[(size_t)TOKENS*DIM];
__device__ float g_hbuf[(size_t)NSLOTS*HID];
__device__ float g_ybuf[(size_t)NSLOTS*DIM];

// ---------------- helpers ----------------
__device__ __forceinline__ uint32_t smem_u32(const void* p) {
    uint32_t a;
    asm("{ .reg .u64 t; cvta.to.shared.u64 t, %1; cvt.u32.u64 %0, t; }" : "=r"(a) : "l"(p));
    return a;
}
__device__ __forceinline__ uint32_t tf32r(float x) {
    uint32_t r; asm("cvt.rna.tf32.f32 %0, %1;" : "=r"(r) : "f"(x)); return r;
}
__device__ __forceinline__ float tf32f(float x) { return __uint_as_float(tf32r(x)); }
__device__ __forceinline__ void mma8(float* d, const uint32_t* a, const uint32_t* b) {
    asm volatile("mma.sync.aligned.m16n8k8.row.col.f32.tf32.tf32.f32 "
        "{%0,%1,%2,%3}, {%4,%5,%6,%7}, {%8,%9}, {%0,%1,%2,%3};"
        : "+f"(d[0]), "+f"(d[1]), "+f"(d[2]), "+f"(d[3])
        : "r"(a[0]), "r"(a[1]), "r"(a[2]), "r"(a[3]), "r"(b[0]), "r"(b[1]));
}
__device__ __forceinline__ void cpa16(uint32_t dst, const float* src) {
    asm volatile("cp.async.cg.shared.global [%0], [%1], 16;" :: "r"(dst), "l"(src));
}
#define CP_COMMIT() asm volatile("cp.async.commit_group;" ::: "memory")
#define CP_WAIT1()  asm volatile("cp.async.wait_group 1;" ::: "memory")
__device__ __forceinline__ float silu(float v) { return v / (1.f + __expf(-v)); }

// ---------------- small kernels ----------------
__global__ void init_kernel() {
    if (threadIdx.x < NEXP) g_cnt[threadIdx.x] = 0;
}

// pre-round x to tf32 AND apply per-8-group column permutation (k0,k4,k1,k5,k2,k6,k3,k7)
__global__ __launch_bounds__(256) void xcvt_kernel(const float* __restrict__ x) {
    int i = blockIdx.x * 256 + threadIdx.x;       // over TOKENS*DIM/8 groups
    const float4* s = (const float4*)(x + (size_t)i * 8);
    float4 u = s[0], v = s[1];                     // u=k0..k3, v=k4..k7
    float4 o0 = make_float4(tf32f(u.x), tf32f(v.x), tf32f(u.y), tf32f(v.y));
    float4 o1 = make_float4(tf32f(u.z), tf32f(v.z), tf32f(u.w), tf32f(v.w));
    float4* d = (float4*)(g_xr + (size_t)i * 8);
    d[0] = o0; d[1] = o1;
}

__global__ __launch_bounds__(256) void route_kernel(const float* __restrict__ x,
                                                    const float* __restrict__ Wg) {
    int t = (blockIdx.x * blockDim.x + threadIdx.x) >> 5;
    int lane = threadIdx.x & 31;
    if (t >= TOKENS) return;
    const float* xr = x + (size_t)t * DIM;
    float acc = 0.f;
    if (lane < NEXP) {
#pragma unroll 8
        for (int d = 0; d < DIM; d++) acc = fmaf(xr[d], Wg[d * NEXP + lane], acc);
    }
    float v0 = -1e30f, v1 = -1e30f;
    int i0 = 0, i1 = 0;
#pragma unroll
    for (int i = 0; i < NEXP; i++) {
        float vi = __shfl_sync(0xffffffffu, acc, i);
        if (vi > v0)      { v1 = v0; i1 = i0; v0 = vi; i0 = i; }
        else if (vi > v1) { v1 = vi; i1 = i; }
    }
    if (lane == 0) {
        float e1 = __expf(v1 - v0);
        float s  = 1.f + e1;
        g_wk[t * 2 + 0] = 1.f / s;
        g_wk[t * 2 + 1] = e1 / s;
        int p0 = atomicAdd(&g_cnt[i0], 1);
        g_list[i0 * TOKENS + p0] = t * 2 + 0;
        int p1 = atomicAdd(&g_cnt[i1], 1);
        g_list[i1 * TOKENS + p1] = t * 2 + 1;
    }
}

// 1 warp: prefix offsets + tile list
__global__ void scan_kernel() {
    int lane = threadIdx.x;
    int c = (lane < NEXP) ? g_cnt[lane] : 0;
    int s = c;
#pragma unroll
    for (int o = 1; o < 32; o <<= 1) {
        int p = __shfl_up_sync(0xffffffffu, s, o);
        if (lane >= o) s += p;
    }
    if (lane < NEXP) g_off[lane] = s - c;
    if (lane == 0) {
        int nt = 0, a = 0;
        for (int e = 0; e < NEXP; e++) {
            int ce = g_cnt[e];
            for (int m = 0; m < ce; m += TMT) {
                g_te[nt] = e; g_tg[nt] = a + m;
                g_tr[nt] = (ce - m < TMT) ? (ce - m) : TMT;
                nt++;
            }
            a += ce;
        }
        g_ntiles = nt;
    }
}

// one block per expert: parallel scatter
__global__ __launch_bounds__(256) void scatter_kernel() {
    int e = blockIdx.x;
    int c = g_cnt[e], o = g_off[e];
    for (int i = threadIdx.x; i < c; i += 256) {
        int sl = g_list[e * TOKENS + i];
        g_perm[o + i] = sl;
        g_inv[sl] = o + i;
        g_rowe[o + i] = e;
    }
}

// ---------------- GEMM1: h = silu(xr @ W1 + b1), fused LN partials ----------------
__global__ __launch_bounds__(256, 2) void gemm1_kernel(const float* __restrict__ W1,
                                                       const float* __restrict__ b1) {
    extern __shared__ float dsm[];
    __shared__ int s_tok[TMT];
    int tile = blockIdx.y;
    if (tile >= g_ntiles) return;
    int e = g_te[tile], gp0 = g_tg[tile], rows = g_tr[tile];
    int n0 = blockIdx.x * 128;
    int tid = threadIdx.x, lane = tid & 31, wid = tid >> 5;
    int g = lane >> 2, tg = lane & 3;
    int wm = wid & 1, wn = wid >> 1;
    uint32_t dynb = smem_u32(dsm);

    if (tid < TMT) {
        int r = (tid < rows) ? tid : rows - 1;
        s_tok[tid] = g_perm[gp0 + r] >> 1;
    }
    __syncthreads();

    const float* pA[4]; uint32_t dA[4];
    const float* pB[4]; uint32_t dB[4];
    const float* Wb = W1 + (size_t)e * DIM * HID + n0;
#pragma unroll
    for (int i = 0; i < 4; i++) {
        int c = tid + 256 * i;
        int row = c >> 3, fo = (c & 7) * 4;
        pA[i] = g_xr + (size_t)s_tok[row] * DIM + fo;
        dA[i] = dynb + (uint32_t)(row * (ASTR * 4) + fo * 4);
        int kr = c >> 5, nc = (c & 31) * 4;
        pB[i] = Wb + (size_t)kr * HID + nc;
        dB[i] = dynb + (uint32_t)(ABYTES + kr * (BSTR * 4) + nc * 4);
    }

    float d[4][4][4];
#pragma unroll
    for (int i = 0; i < 4; i++)
#pragma unroll
        for (int j = 0; j < 4; j++)
#pragma unroll
            for (int c = 0; c < 4; c++) d[i][j][c] = 0.f;

    const int S = DIM / KC;   // 16
#pragma unroll
    for (int ps = 0; ps < 2; ps++) {
#pragma unroll
        for (int i = 0; i < 4; i++) {
            cpa16(dA[i] + ps * SBYTES, pA[i] + ps * KC);
            cpa16(dB[i] + ps * SBYTES, pB[i] + (size_t)ps * KC * HID);
        }
        CP_COMMIT();
    }

    int st = 0, si = 2;
    for (int s = 0; s < S; s++) {
        CP_WAIT1();
        __syncthreads();
        if (s + 2 < S) {
            int k0 = (s + 2) * KC;
#pragma unroll
            for (int i = 0; i < 4; i++) {
                cpa16(dA[i] + si * SBYTES, pA[i] + k0);
                cpa16(dB[i] + si * SBYTES, pB[i] + (size_t)k0 * HID);
            }
        }
        CP_COMMIT();
        const float* Ab = dsm + st * SFLOAT;
        const float* Bb = Ab + AFLOAT;
#pragma unroll
        for (int k8 = 0; k8 < KC; k8 += 8) {
            uint32_t af[4][4], bf[4][2];
#pragma unroll
            for (int mf = 0; mf < 4; mf++) {
                const float* ap = Ab + (wm * 64 + mf * 16 + g) * ASTR + k8 + 2 * tg;
                float2 lo = *(const float2*)ap;
                float2 hi = *(const float2*)(ap + 8 * ASTR);
                af[mf][0] = __float_as_uint(lo.x);
                af[mf][1] = __float_as_uint(hi.x);
                af[mf][2] = __float_as_uint(lo.y);
                af[mf][3] = __float_as_uint(hi.y);
            }
#pragma unroll
            for (int nf = 0; nf < 4; nf++) {
                const float* bp = Bb + (k8 + tg) * BSTR + wn * 32 + nf * 8 + g;
                bf[nf][0] = tf32r(bp[0]);
                bf[nf][1] = tf32r(bp[4 * BSTR]);
            }
#pragma unroll
            for (int mf = 0; mf < 4; mf++)
#pragma unroll
                for (int nf = 0; nf < 4; nf++)
                    mma8(d[mf][nf], af[mf], bf[nf]);
        }
        st = (st == 2) ? 0 : st + 1;
        si = (si == 2) ? 0 : si + 1;
    }
    __syncthreads();
    float* s_sum = dsm;
    float* s_sq  = dsm + 512;

    const float* brow = b1 + (size_t)e * HID + n0;
    float bias[4][2];
#pragma unroll
    for (int nf = 0; nf < 4; nf++) {
        int n = wn * 32 + nf * 8 + tg * 2;
        bias[nf][0] = brow[n];
        bias[nf][1] = brow[n + 1];
    }
#pragma unroll
    for (int mf = 0; mf < 4; mf++) {
#pragma unroll
        for (int h = 0; h < 2; h++) {
            int lr = wm * 64 + mf * 16 + g + 8 * h;
            bool val = (lr < rows);
            int gp = gp0 + lr;
            float ss = 0.f, qq = 0.f;
            float* hrow = g_hbuf + (size_t)gp * HID + n0;
#pragma unroll
            for (int nf = 0; nf < 4; nf++) {
                float v0 = silu(d[mf][nf][2 * h + 0] + bias[nf][0]);
                float v1 = silu(d[mf][nf][2 * h + 1] + bias[nf][1]);
                ss += v0 + v1;
                qq += v0 * v0 + v1 * v1;
                if (val) {
                    *(float2*)(hrow + wn * 32 + nf * 8 + tg * 2) = make_float2(v0, v1);
                }
            }
            ss += __shfl_xor_sync(0xffffffffu, ss, 1);
            ss += __shfl_xor_sync(0xffffffffu, ss, 2);
            qq += __shfl_xor_sync(0xffffffffu, qq, 1);
            qq += __shfl_xor_sync(0xffffffffu, qq, 2);
            if (tg == 0) { s_sum[wn * TMT + lr] = ss; s_sq[wn * TMT + lr] = qq; }
        }
    }
    __syncthreads();
    if (tid < TMT && tid < rows) {
        float ts = s_sum[tid] + s_sum[TMT + tid] + s_sum[2 * TMT + tid] + s_sum[3 * TMT + tid];
        float tq = s_sq[tid] + s_sq[TMT + tid] + s_sq[2 * TMT + tid] + s_sq[3 * TMT + tid];
        g_psum[(size_t)(gp0 + tid) * NB1 + blockIdx.x] = ts;
        g_psq [(size_t)(gp0 + tid) * NB1 + blockIdx.x] = tq;
    }
}

// ---------------- lnfix: stats + LN + tf32 round + permute, in place ----------------
__global__ __launch_bounds__(256) void lnfix_kernel(const float* __restrict__ ln_g,
                                                    const float* __restrict__ ln_b) {
    __shared__ float smu, srs;
    int gp = blockIdx.x;
    int tid = threadIdx.x;
    int e = g_rowe[gp];
    if (tid < 32) {
        float s = (tid < NB1) ? g_psum[(size_t)gp * NB1 + tid] : 0.f;
        float q = (tid < NB1) ? g_psq [(size_t)gp * NB1 + tid] : 0.f;
#pragma unroll
        for (int o = 8; o; o >>= 1) {
            s += __shfl_xor_sync(0xffffffffu, s, o);
            q += __shfl_xor_sync(0xffffffffu, q, o);
        }
        if (tid == 0) {
            float mu = s * (1.f / HID);
            float var = q * (1.f / HID) - mu * mu;
            smu = mu;
            srs = rsqrtf(var + 1e-5f);
        }
    }
    __syncthreads();
    float mu = smu, rs = srs;
    float4* h = (float4*)(g_hbuf + (size_t)gp * HID);
    const float4* gg = (const float4*)(ln_g + (size_t)e * HID);
    const float4* bb = (const float4*)(ln_b + (size_t)e * HID);
    // thread handles one 8-group: idx4 = tid*2, tid*2+1 ; write permuted
    int i0 = tid * 2, i1 = tid * 2 + 1;
    float4 u = h[i0], v = h[i1];
    float4 Gu = gg[i0], Gv = gg[i1];
    float4 Bu = bb[i0], Bv = bb[i1];
    float t0 = tf32f((u.x - mu) * rs * Gu.x + Bu.x);
    float t1 = tf32f((u.y - mu) * rs * Gu.y + Bu.y);
    float t2 = tf32f((u.z - mu) * rs * Gu.z + Bu.z);
    float t3 = tf32f((u.w - mu) * rs * Gu.w + Bu.w);
    float t4 = tf32f((v.x - mu) * rs * Gv.x + Bv.x);
    float t5 = tf32f((v.y - mu) * rs * Gv.y + Bv.y);
    float t6 = tf32f((v.z - mu) * rs * Gv.z + Bv.z);
    float t7 = tf32f((v.w - mu) * rs * Gv.w + Bv.w);
    h[i0] = make_float4(t0, t4, t1, t5);
    h[i1] = make_float4(t2, t6, t3, t7);
}

// ---------------- GEMM2: y = hfix @ W2 + b2, × gate weight ----------------
__global__ __launch_bounds__(256, 2) void gemm2_kernel(const float* __restrict__ W2,
                                                       const float* __restrict__ b2) {
    extern __shared__ float dsm[];
    __shared__ int s_gp[TMT];
    __shared__ float s_w[TMT];
    int tile = blockIdx.y;
    if (tile >= g_ntiles) return;
    int e = g_te[tile], gp0 = g_tg[tile], rows = g_tr[tile];
    int n0 = blockIdx.x * 128;
    int tid = threadIdx.x, lane = tid & 31, wid = tid >> 5;
    int g = lane >> 2, tg = lane & 3;
    int wm = wid & 1, wn = wid >> 1;
    uint32_t dynb = smem_u32(dsm);

    if (tid < TMT) {
        int r = (tid < rows) ? tid : rows - 1;
        s_gp[tid] = gp0 + r;
        s_w[tid] = (tid < rows) ? g_wk[g_perm[gp0 + tid]] : 0.f;
    }
    __syncthreads();

    const float* pA[4]; uint32_t dA[4];
    const float* pB[4]; uint32_t dB[4];
    const float* Wb = W2 + (size_t)e * HID * DIM + n0;
#pragma unroll
    for (int i = 0; i < 4; i++) {
        int c = tid + 256 * i;
        int row = c >> 3, fo = (c & 7) * 4;
        pA[i] = g_hbuf + (size_t)s_gp[row] * HID + fo;
        dA[i] = dynb + (uint32_t)(row * (ASTR * 4) + fo * 4);
        int kr = c >> 5, nc = (c & 31) * 4;
        pB[i] = Wb + (size_t)kr * DIM + nc;
        dB[i] = dynb + (uint32_t)(ABYTES + kr * (BSTR * 4) + nc * 4);
    }

    float d[4][4][4];
#pragma unroll
    for (int i = 0; i < 4; i++)
#pragma unroll
        for (int j = 0; j < 4; j++)
#pragma unroll
            for (int c = 0; c < 4; c++) d[i][j][c] = 0.f;

    const int S = HID / KC;   // 64
#pragma unroll
    for (int ps = 0; ps < 2; ps++) {
#pragma unroll
        for (int i = 0; i < 4; i++) {
            cpa16(dA[i] + ps * SBYTES, pA[i] + ps * KC);
            cpa16(dB[i] + ps * SBYTES, pB[i] + (size_t)ps * KC * DIM);
        }
        CP_COMMIT();
    }

    int st = 0, si = 2;
    for (int s = 0; s < S; s++) {
        CP_WAIT1();
        __syncthreads();
        if (s + 2 < S) {
            int k0 = (s + 2) * KC;
#pragma unroll
            for (int i = 0; i < 4; i++) {
                cpa16(dA[i] + si * SBYTES, pA[i] + k0);
                cpa16(dB[i] + si * SBYTES, pB[i] + (size_t)k0 * DIM);
            }
        }
        CP_COMMIT();
        const float* Ab = dsm + st * SFLOAT;
        const float* Bb = Ab + AFLOAT;
#pragma unroll
        for (int k8 = 0; k8 < KC; k8 += 8) {
            uint32_t af[4][4], bf[4][2];
#pragma unroll
            for (int mf = 0; mf < 4; mf++) {
                const float* ap = Ab + (wm * 64 + mf * 16 + g) * ASTR + k8 + 2 * tg;
                float2 lo = *(const float2*)ap;
                float2 hi = *(const float2*)(ap + 8 * ASTR);
                af[mf][0] = __float_as_uint(lo.x);
                af[mf][1] = __float_as_uint(hi.x);
                af[mf][2] = __float_as_uint(lo.y);
                af[mf][3] = __float_as_uint(hi.y);
            }
#pragma unroll
            for (int nf = 0; nf < 4; nf++) {
                const float* bp = Bb + (k8 + tg) * BSTR + wn * 32 + nf * 8 + g;
                bf[nf][0] = tf32r(bp[0]);
                bf[nf][1] = tf32r(bp[4 * BSTR]);
            }
#pragma unroll
            for (int mf = 0; mf < 4; mf++)
#pragma unroll
                for (int nf = 0; nf < 4; nf++)
                    mma8(d[mf][nf], af[mf], bf[nf]);
        }
        st = (st == 2) ? 0 : st + 1;
        si = (si == 2) ? 0 : si + 1;
    }

    const float* brow = b2 + (size_t)e * DIM + n0;
    float bias[4][2];
#pragma unroll
    for (int nf = 0; nf < 4; nf++) {
        int n = wn * 32 + nf * 8 + tg * 2;
        bias[nf][0] = brow[n];
        bias[nf][1] = brow[n + 1];
    }
#pragma unroll
    for (int mf = 0; mf < 4; mf++) {
#pragma unroll
        for (int h = 0; h < 2; h++) {
            int lr = wm * 64 + mf * 16 + g + 8 * h;
            if (lr >= rows) continue;
            int gp = gp0 + lr;
            float w = s_w[lr];
            float* yrow = g_ybuf + (size_t)gp * DIM + n0;
#pragma unroll
            for (int nf = 0; nf < 4; nf++) {
                float v0 = (d[mf][nf][2 * h + 0] + bias[nf][0]) * w;
                float v1 = (d[mf][nf][2 * h + 1] + bias[nf][1]) * w;
                *(float2*)(yrow + wn * 32 + nf * 8 + tg * 2) = make_float2(v0, v1);
            }
        }
    }
}

__global__ __launch_bounds__(256) void combine_kernel(float* __restrict__ out) {
    int i = blockIdx.x * 256 + threadIdx.x;
    int t = i >> 7;
    int d4 = (i & 127) * 4;
    int p0 = g_inv[t * 2 + 0];
    int p1 = g_inv[t * 2 + 1];
    float4 a = *(const float4*)&g_ybuf[(size_t)p0 * DIM + d4];
    float4 b = *(const float4*)&g_ybuf[(size_t)p1 * DIM + d4];
    *(float4*)&out[(size_t)t * DIM + d4] =
        make_float4(a.x + b.x, a.y + b.y, a.z + b.z, a.w + b.w);
}

extern "C" void kernel_launch(void* const* d_in, const int* in_sizes, int n_in,
                              void* d_out, int out_size) {
    const float* x    = (const float*)d_in[0];
    const float* Wg   = (const float*)d_in[1];
    const float* W1   = (const float*)d_in[2];
    const float* b1   = (const float*)d_in[3];
    const float* ln_g = (const float*)d_in[4];
    const float* ln_b = (const float*)d_in[5];
    const float* W2   = (const float*)d_in[6];
    const float* b2   = (const float*)d_in[7];
    float* out = (float*)d_out;

    cudaFuncSetAttribute(gemm1_kernel, cudaFuncAttributeMaxDynamicSharedMemorySize, 3 * SBYTES);
    cudaFuncSetAttribute(gemm2_kernel, cudaFuncAttributeMaxDynamicSharedMemorySize, 3 * SBYTES);

    init_kernel<<<1, 32>>>();
    xcvt_kernel<<<TOKENS * DIM / 8 / 256, 256>>>(x);
    route_kernel<<<(TOKENS * 32 + 255) / 256, 256>>>(x, Wg);
    scan_kernel<<<1, 32>>>();
    scatter_kernel<<<NEXP, 256>>>();
    gemm1_kernel<<<dim3(NB1, MAXT), 256, 3 * SBYTES>>>(W1, b1);
    lnfix_kernel<<<NSLOTS, 256>>>(ln_g, ln_b);
    gemm2_kernel<<<dim3(NB2, MAXT), 256, 3 * SBYTES>>>(W2, b2);
    combine_kernel<<<TOKENS * DIM / 4 / 256, 256>>>(out);
}

// round 6
// speedup vs baseline: 2.1429x; 1.1861x over previous
#include <cuda_runtime.h>
#include <cstdint>
#include <math.h>

#define TOKENS 2048
#define DIM    512
#define NEXP   16
#define HID    2048
#define NSLOTS (TOKENS*2)
#define TMT    128
#define KC     32
#define MAXT   48
#define TM2    64
#define MAXT2  80
#define NB1    (HID/128)   // 16
#define NB2    (DIM/128)   // 4
#define ASTR   40
#define BSTR   136
#define ABYTES (128*ASTR*4)              // 20480
#define SBYTES (ABYTES + KC*BSTR*4)      // 37888
#define SFLOAT (SBYTES/4)
#define AFLOAT (ABYTES/4)
#define ABYTES2 (64*ASTR*4)              // 10240
#define SBYTES2 (ABYTES2 + KC*BSTR*4)    // 27648
#define SFLOAT2 (SBYTES2/4)
#define AFLOAT2 (ABYTES2/4)

// ---------------- device scratch ----------------
__device__ int   g_cnt[NEXP];
__device__ int   g_list[NEXP*TOKENS];
__device__ float g_wk[NSLOTS];
__device__ int   g_perm[NSLOTS];
__device__ int   g_inv[NSLOTS];
__device__ int   g_rowe[NSLOTS];
__device__ int   g_te[MAXT], g_tg[MAXT], g_tr[MAXT];
__device__ int   g_ntiles;
__device__ int   g_te2[MAXT2], g_tg2[MAXT2], g_tr2[MAXT2];
__device__ int   g_ntiles2;
__device__ float g_psum[NSLOTS*NB1], g_psq[NSLOTS*NB1];
__device__ float g_xr[(size_t)TOKENS*DIM];
__device__ float g_hbuf[(size_t)NSLOTS*HID];
__device__ float g_ybuf[(size_t)NSLOTS*DIM];

// ---------------- helpers ----------------
__device__ __forceinline__ uint32_t smem_u32(const void* p) {
    uint32_t a;
    asm("{ .reg .u64 t; cvta.to.shared.u64 t, %1; cvt.u32.u64 %0, t; }" : "=r"(a) : "l"(p));
    return a;
}
__device__ __forceinline__ uint32_t tf32r(float x) {
    uint32_t r; asm("cvt.rna.tf32.f32 %0, %1;" : "=r"(r) : "f"(x)); return r;
}
__device__ __forceinline__ float tf32f(float x) { return __uint_as_float(tf32r(x)); }
__device__ __forceinline__ void mma8(float* d, const uint32_t* a, const uint32_t* b) {
    asm volatile("mma.sync.aligned.m16n8k8.row.col.f32.tf32.tf32.f32 "
        "{%0,%1,%2,%3}, {%4,%5,%6,%7}, {%8,%9}, {%0,%1,%2,%3};"
        : "+f"(d[0]), "+f"(d[1]), "+f"(d[2]), "+f"(d[3])
        : "r"(a[0]), "r"(a[1]), "r"(a[2]), "r"(a[3]), "r"(b[0]), "r"(b[1]));
}
__device__ __forceinline__ void cpa16(uint32_t dst, const float* src) {
    asm volatile("cp.async.cg.shared.global [%0], [%1], 16;" :: "r"(dst), "l"(src));
}
#define CP_COMMIT() asm volatile("cp.async.commit_group;" ::: "memory")
#define CP_WAIT1()  asm volatile("cp.async.wait_group 1;" ::: "memory")
__device__ __forceinline__ float silu(float v) { return v / (1.f + __expf(-v)); }

// ---------------- small kernels ----------------
__global__ void init_kernel() {
    if (threadIdx.x < NEXP) g_cnt[threadIdx.x] = 0;
}

__global__ __launch_bounds__(256) void xcvt_kernel(const float* __restrict__ x) {
    int i = blockIdx.x * 256 + threadIdx.x;
    const float4* s = (const float4*)(x + (size_t)i * 8);
    float4 u = s[0], v = s[1];
    float4 o0 = make_float4(tf32f(u.x), tf32f(v.x), tf32f(u.y), tf32f(v.y));
    float4 o1 = make_float4(tf32f(u.z), tf32f(v.z), tf32f(u.w), tf32f(v.w));
    float4* d = (float4*)(g_xr + (size_t)i * 8);
    d[0] = o0; d[1] = o1;
}

__global__ __launch_bounds__(256) void route_kernel(const float* __restrict__ x,
                                                    const float* __restrict__ Wg) {
    int t = (blockIdx.x * blockDim.x + threadIdx.x) >> 5;
    int lane = threadIdx.x & 31;
    if (t >= TOKENS) return;
    const float* xr = x + (size_t)t * DIM;
    float acc = 0.f;
    if (lane < NEXP) {
#pragma unroll 8
        for (int d = 0; d < DIM; d++) acc = fmaf(xr[d], Wg[d * NEXP + lane], acc);
    }
    float v0 = -1e30f, v1 = -1e30f;
    int i0 = 0, i1 = 0;
#pragma unroll
    for (int i = 0; i < NEXP; i++) {
        float vi = __shfl_sync(0xffffffffu, acc, i);
        if (vi > v0)      { v1 = v0; i1 = i0; v0 = vi; i0 = i; }
        else if (vi > v1) { v1 = vi; i1 = i; }
    }
    if (lane == 0) {
        float e1 = __expf(v1 - v0);
        float s  = 1.f + e1;
        g_wk[t * 2 + 0] = 1.f / s;
        g_wk[t * 2 + 1] = e1 / s;
        int p0 = atomicAdd(&g_cnt[i0], 1);
        g_list[i0 * TOKENS + p0] = t * 2 + 0;
        int p1 = atomicAdd(&g_cnt[i1], 1);
        g_list[i1 * TOKENS + p1] = t * 2 + 1;
    }
}

// one block per expert: parallel scatter; block 0 also builds tile lists
__global__ __launch_bounds__(256) void scatter_kernel() {
    int e = blockIdx.x;
    int o = 0;
#pragma unroll
    for (int j = 0; j < NEXP; j++) {
        int cj = g_cnt[j];
        if (j < e) o += cj;
    }
    int c = g_cnt[e];
    for (int i = threadIdx.x; i < c; i += 256) {
        int sl = g_list[e * TOKENS + i];
        g_perm[o + i] = sl;
        g_inv[sl] = o + i;
        g_rowe[o + i] = e;
    }
    if (e == 0 && threadIdx.x == 0) {
        int nt = 0, nt2 = 0, a = 0;
        for (int ee = 0; ee < NEXP; ee++) {
            int ce = g_cnt[ee];
            for (int m = 0; m < ce; m += TMT) {
                g_te[nt] = ee; g_tg[nt] = a + m;
                g_tr[nt] = (ce - m < TMT) ? (ce - m) : TMT;
                nt++;
            }
            for (int m = 0; m < ce; m += TM2) {
                g_te2[nt2] = ee; g_tg2[nt2] = a + m;
                g_tr2[nt2] = (ce - m < TM2) ? (ce - m) : TM2;
                nt2++;
            }
            a += ce;
        }
        g_ntiles = nt;
        g_ntiles2 = nt2;
    }
}

// ---------------- GEMM1: h = silu(xr @ W1 + b1), fused LN partials ----------------
__global__ __launch_bounds__(256, 2) void gemm1_kernel(const float* __restrict__ W1,
                                                       const float* __restrict__ b1) {
    extern __shared__ float dsm[];
    __shared__ int s_tok[TMT];
    int tile = blockIdx.y;
    if (tile >= g_ntiles) return;
    int e = g_te[tile], gp0 = g_tg[tile], rows = g_tr[tile];
    int n0 = blockIdx.x * 128;
    int tid = threadIdx.x, lane = tid & 31, wid = tid >> 5;
    int g = lane >> 2, tg = lane & 3;
    int wm = wid & 1, wn = wid >> 1;
    uint32_t dynb = smem_u32(dsm);

    if (tid < TMT) {
        int r = (tid < rows) ? tid : rows - 1;
        s_tok[tid] = g_perm[gp0 + r] >> 1;
    }
    __syncthreads();

    const float* pA[4]; uint32_t dA[4];
    const float* pB[4]; uint32_t dB[4];
    const float* Wb = W1 + (size_t)e * DIM * HID + n0;
#pragma unroll
    for (int i = 0; i < 4; i++) {
        int c = tid + 256 * i;
        int row = c >> 3, fo = (c & 7) * 4;
        pA[i] = g_xr + (size_t)s_tok[row] * DIM + fo;
        dA[i] = dynb + (uint32_t)(row * (ASTR * 4) + fo * 4);
        int kr = c >> 5, nc = (c & 31) * 4;
        pB[i] = Wb + (size_t)kr * HID + nc;
        dB[i] = dynb + (uint32_t)(ABYTES + kr * (BSTR * 4) + nc * 4);
    }

    float d[4][4][4];
#pragma unroll
    for (int i = 0; i < 4; i++)
#pragma unroll
        for (int j = 0; j < 4; j++)
#pragma unroll
            for (int c = 0; c < 4; c++) d[i][j][c] = 0.f;

    const int S = DIM / KC;   // 16
#pragma unroll
    for (int ps = 0; ps < 2; ps++) {
#pragma unroll
        for (int i = 0; i < 4; i++) {
            cpa16(dA[i] + ps * SBYTES, pA[i] + ps * KC);
            cpa16(dB[i] + ps * SBYTES, pB[i] + (size_t)ps * KC * HID);
        }
        CP_COMMIT();
    }

    int st = 0, si = 2;
    for (int s = 0; s < S; s++) {
        CP_WAIT1();
        __syncthreads();
        if (s + 2 < S) {
            int k0 = (s + 2) * KC;
#pragma unroll
            for (int i = 0; i < 4; i++) {
                cpa16(dA[i] + si * SBYTES, pA[i] + k0);
                cpa16(dB[i] + si * SBYTES, pB[i] + (size_t)k0 * HID);
            }
        }
        CP_COMMIT();
        const float* Ab = dsm + st * SFLOAT;
        const float* Bb = Ab + AFLOAT;
#pragma unroll
        for (int k8 = 0; k8 < KC; k8 += 8) {
            uint32_t af[4][4], bf[4][2];
#pragma unroll
            for (int mf = 0; mf < 4; mf++) {
                const float* ap = Ab + (wm * 64 + mf * 16 + g) * ASTR + k8 + 2 * tg;
                float2 lo = *(const float2*)ap;
                float2 hi = *(const float2*)(ap + 8 * ASTR);
                af[mf][0] = __float_as_uint(lo.x);
                af[mf][1] = __float_as_uint(hi.x);
                af[mf][2] = __float_as_uint(lo.y);
                af[mf][3] = __float_as_uint(hi.y);
            }
#pragma unroll
            for (int nf = 0; nf < 4; nf++) {
                const float* bp = Bb + (k8 + tg) * BSTR + wn * 32 + nf * 8 + g;
                bf[nf][0] = tf32r(bp[0]);
                bf[nf][1] = tf32r(bp[4 * BSTR]);
            }
#pragma unroll
            for (int mf = 0; mf < 4; mf++)
#pragma unroll
                for (int nf = 0; nf < 4; nf++)
                    mma8(d[mf][nf], af[mf], bf[nf]);
        }
        st = (st == 2) ? 0 : st + 1;
        si = (si == 2) ? 0 : si + 1;
    }
    __syncthreads();
    float* s_sum = dsm;
    float* s_sq  = dsm + 512;

    const float* brow = b1 + (size_t)e * HID + n0;
    float bias[4][2];
#pragma unroll
    for (int nf = 0; nf < 4; nf++) {
        int n = wn * 32 + nf * 8 + tg * 2;
        bias[nf][0] = brow[n];
        bias[nf][1] = brow[n + 1];
    }
#pragma unroll
    for (int mf = 0; mf < 4; mf++) {
#pragma unroll
        for (int h = 0; h < 2; h++) {
            int lr = wm * 64 + mf * 16 + g + 8 * h;
            bool val = (lr < rows);
            int gp = gp0 + lr;
            float ss = 0.f, qq = 0.f;
            float* hrow = g_hbuf + (size_t)gp * HID + n0;
#pragma unroll
            for (int nf = 0; nf < 4; nf++) {
                float v0 = silu(d[mf][nf][2 * h + 0] + bias[nf][0]);
                float v1 = silu(d[mf][nf][2 * h + 1] + bias[nf][1]);
                ss += v0 + v1;
                qq += v0 * v0 + v1 * v1;
                if (val) {
                    *(float2*)(hrow + wn * 32 + nf * 8 + tg * 2) = make_float2(v0, v1);
                }
            }
            ss += __shfl_xor_sync(0xffffffffu, ss, 1);
            ss += __shfl_xor_sync(0xffffffffu, ss, 2);
            qq += __shfl_xor_sync(0xffffffffu, qq, 1);
            qq += __shfl_xor_sync(0xffffffffu, qq, 2);
            if (tg == 0) { s_sum[wn * TMT + lr] = ss; s_sq[wn * TMT + lr] = qq; }
        }
    }
    __syncthreads();
    if (tid < TMT && tid < rows) {
        float ts = s_sum[tid] + s_sum[TMT + tid] + s_sum[2 * TMT + tid] + s_sum[3 * TMT + tid];
        float tq = s_sq[tid] + s_sq[TMT + tid] + s_sq[2 * TMT + tid] + s_sq[3 * TMT + tid];
        g_psum[(size_t)(gp0 + tid) * NB1 + blockIdx.x] = ts;
        g_psq [(size_t)(gp0 + tid) * NB1 + blockIdx.x] = tq;
    }
}

// ---------------- lnfix: stats + LN + tf32 round + permute, in place ----------------
__global__ __launch_bounds__(256) void lnfix_kernel(const float* __restrict__ ln_g,
                                                    const float* __restrict__ ln_b) {
    __shared__ float smu, srs;
    int gp = blockIdx.x;
    int tid = threadIdx.x;
    int e = g_rowe[gp];
    if (tid < 32) {
        float s = (tid < NB1) ? g_psum[(size_t)gp * NB1 + tid] : 0.f;
        float q = (tid < NB1) ? g_psq [(size_t)gp * NB1 + tid] : 0.f;
#pragma unroll
        for (int o = 8; o; o >>= 1) {
            s += __shfl_xor_sync(0xffffffffu, s, o);
            q += __shfl_xor_sync(0xffffffffu, q, o);
        }
        if (tid == 0) {
            float mu = s * (1.f / HID);
            float var = q * (1.f / HID) - mu * mu;
            smu = mu;
            srs = rsqrtf(var + 1e-5f);
        }
    }
    __syncthreads();
    float mu = smu, rs = srs;
    float4* h = (float4*)(g_hbuf + (size_t)gp * HID);
    const float4* gg = (const float4*)(ln_g + (size_t)e * HID);
    const float4* bb = (const float4*)(ln_b + (size_t)e * HID);
    int i0 = tid * 2, i1 = tid * 2 + 1;
    float4 u = h[i0], v = h[i1];
    float4 Gu = gg[i0], Gv = gg[i1];
    float4 Bu = bb[i0], Bv = bb[i1];
    float t0 = tf32f((u.x - mu) * rs * Gu.x + Bu.x);
    float t1 = tf32f((u.y - mu) * rs * Gu.y + Bu.y);
    float t2 = tf32f((u.z - mu) * rs * Gu.z + Bu.z);
    float t3 = tf32f((u.w - mu) * rs * Gu.w + Bu.w);
    float t4 = tf32f((v.x - mu) * rs * Gv.x + Bv.x);
    float t5 = tf32f((v.y - mu) * rs * Gv.y + Bv.y);
    float t6 = tf32f((v.z - mu) * rs * Gv.z + Bv.z);
    float t7 = tf32f((v.w - mu) * rs * Gv.w + Bv.w);
    h[i0] = make_float4(t0, t4, t1, t5);
    h[i1] = make_float4(t2, t6, t3, t7);
}

// ---------------- GEMM2 (TM=64): y = hfix @ W2 + b2, × gate weight ----------------
__global__ __launch_bounds__(256, 2) void gemm2_kernel(const float* __restrict__ W2,
                                                       const float* __restrict__ b2) {
    extern __shared__ float dsm[];
    __shared__ int s_gp[TM2];
    __shared__ float s_w[TM2];
    int tile = blockIdx.y;
    if (tile >= g_ntiles2) return;
    int e = g_te2[tile], gp0 = g_tg2[tile], rows = g_tr2[tile];
    int n0 = blockIdx.x * 128;
    int tid = threadIdx.x, lane = tid & 31, wid = tid >> 5;
    int g = lane >> 2, tg = lane & 3;
    int wm = wid & 1, wn = wid >> 1;
    uint32_t dynb = smem_u32(dsm);

    if (tid < TM2) {
        int r = (tid < rows) ? tid : rows - 1;
        s_gp[tid] = gp0 + r;
        s_w[tid] = (tid < rows) ? g_wk[g_perm[gp0 + tid]] : 0.f;
    }
    __syncthreads();

    const float* pA[2]; uint32_t dA[2];
    const float* pB[4]; uint32_t dB[4];
    const float* Wb = W2 + (size_t)e * HID * DIM + n0;
#pragma unroll
    for (int i = 0; i < 2; i++) {
        int c = tid + 256 * i;
        int row = c >> 3, fo = (c & 7) * 4;
        pA[i] = g_hbuf + (size_t)s_gp[row] * HID + fo;
        dA[i] = dynb + (uint32_t)(row * (ASTR * 4) + fo * 4);
    }
#pragma unroll
    for (int i = 0; i < 4; i++) {
        int c = tid + 256 * i;
        int kr = c >> 5, nc = (c & 31) * 4;
        pB[i] = Wb + (size_t)kr * DIM + nc;
        dB[i] = dynb + (uint32_t)(ABYTES2 + kr * (BSTR * 4) + nc * 4);
    }

    float d[2][4][4];
#pragma unroll
    for (int i = 0; i < 2; i++)
#pragma unroll
        for (int j = 0; j < 4; j++)
#pragma unroll
            for (int c = 0; c < 4; c++) d[i][j][c] = 0.f;

    const int S = HID / KC;   // 64
#pragma unroll
    for (int ps = 0; ps < 2; ps++) {
#pragma unroll
        for (int i = 0; i < 2; i++)
            cpa16(dA[i] + ps * SBYTES2, pA[i] + ps * KC);
#pragma unroll
        for (int i = 0; i < 4; i++)
            cpa16(dB[i] + ps * SBYTES2, pB[i] + (size_t)ps * KC * DIM);
        CP_COMMIT();
    }

    int st = 0, si = 2;
    for (int s = 0; s < S; s++) {
        CP_WAIT1();
        __syncthreads();
        if (s + 2 < S) {
            int k0 = (s + 2) * KC;
#pragma unroll
            for (int i = 0; i < 2; i++)
                cpa16(dA[i] + si * SBYTES2, pA[i] + k0);
#pragma unroll
            for (int i = 0; i < 4; i++)
                cpa16(dB[i] + si * SBYTES2, pB[i] + (size_t)k0 * DIM);
        }
        CP_COMMIT();
        const float* Ab = dsm + st * SFLOAT2;
        const float* Bb = Ab + AFLOAT2;
#pragma unroll
        for (int k8 = 0; k8 < KC; k8 += 8) {
            uint32_t af[2][4], bf[4][2];
#pragma unroll
            for (int mf = 0; mf < 2; mf++) {
                const float* ap = Ab + (wm * 32 + mf * 16 + g) * ASTR + k8 + 2 * tg;
                float2 lo = *(const float2*)ap;
                float2 hi = *(const float2*)(ap + 8 * ASTR);
                af[mf][0] = __float_as_uint(lo.x);
                af[mf][1] = __float_as_uint(hi.x);
                af[mf][2] = __float_as_uint(lo.y);
                af[mf][3] = __float_as_uint(hi.y);
            }
#pragma unroll
            for (int nf = 0; nf < 4; nf++) {
                const float* bp = Bb + (k8 + tg) * BSTR + wn * 32 + nf * 8 + g;
                bf[nf][0] = tf32r(bp[0]);
                bf[nf][1] = tf32r(bp[4 * BSTR]);
            }
#pragma unroll
            for (int mf = 0; mf < 2; mf++)
#pragma unroll
                for (int nf = 0; nf < 4; nf++)
                    mma8(d[mf][nf], af[mf], bf[nf]);
        }
        st = (st == 2) ? 0 : st + 1;
        si = (si == 2) ? 0 : si + 1;
    }

    const float* brow = b2 + (size_t)e * DIM + n0;
    float bias[4][2];
#pragma unroll
    for (int nf = 0; nf < 4; nf++) {
        int n = wn * 32 + nf * 8 + tg * 2;
        bias[nf][0] = brow[n];
        bias[nf][1] = brow[n + 1];
    }
#pragma unroll
    for (int mf = 0; mf < 2; mf++) {
#pragma unroll
        for (int h = 0; h < 2; h++) {
            int lr = wm * 32 + mf * 16 + g + 8 * h;
            if (lr >= rows) continue;
            int gp = gp0 + lr;
            float w = s_w[lr];
            float* yrow = g_ybuf + (size_t)gp * DIM + n0;
#pragma unroll
            for (int nf = 0; nf < 4; nf++) {
                float v0 = (d[mf][nf][2 * h + 0] + bias[nf][0]) * w;
                float v1 = (d[mf][nf][2 * h + 1] + bias[nf][1]) * w;
                *(float2*)(yrow + wn * 32 + nf * 8 + tg * 2) = make_float2(v0, v1);
            }
        }
    }
}

__global__ __launch_bounds__(256) void combine_kernel(float* __restrict__ out) {
    int i = blockIdx.x * 256 + threadIdx.x;
    int t = i >> 7;
    int d4 = (i & 127) * 4;
    int p0 = g_inv[t * 2 + 0];
    int p1 = g_inv[t * 2 + 1];
    float4 a = *(const float4*)&g_ybuf[(size_t)p0 * DIM + d4];
    float4 b = *(const float4*)&g_ybuf[(size_t)p1 * DIM + d4];
    *(float4*)&out[(size_t)t * DIM + d4] =
        make_float4(a.x + b.x, a.y + b.y, a.z + b.z, a.w + b.w);
}

extern "C" void kernel_launch(void* const* d_in, const int* in_sizes, int n_in,
                              void* d_out, int out_size) {
    const float* x    = (const float*)d_in[0];
    const float* Wg   = (const float*)d_in[1];
    const float* W1   = (const float*)d_in[2];
    const float* b1   = (const float*)d_in[3];
    const float* ln_g = (const float*)d_in[4];
    const float* ln_b = (const float*)d_in[5];
    const float* W2   = (const float*)d_in[6];
    const float* b2   = (const float*)d_in[7];
    float* out = (float*)d_out;

    cudaFuncSetAttribute(gemm1_kernel, cudaFuncAttributeMaxDynamicSharedMemorySize, 3 * SBYTES);
    cudaFuncSetAttribute(gemm2_kernel, cudaFuncAttributeMaxDynamicSharedMemorySize, 3 * SBYTES2);

    init_kernel<<<1, 32>>>();
    xcvt_kernel<<<TOKENS * DIM / 8 / 256, 256>>>(x);
    route_kernel<<<(TOKENS * 32 + 255) / 256, 256>>>(x, Wg);
    scatter_kernel<<<NEXP, 256>>>();
    gemm1_kernel<<<dim3(NB1, MAXT), 256, 3 * SBYTES>>>(W1, b1);
    lnfix_kernel<<<NSLOTS, 256>>>(ln_g, ln_b);
    gemm2_kernel<<<dim3(NB2, MAXT2), 256, 3 * SBYTES2>>>(W2, b2);
    combine_kernel<<<TOKENS * DIM / 4 / 256, 256>>>(out);
}

// round 7
// speedup vs baseline: 2.1757x; 1.0153x over previous
#include <cuda_runtime.h>
#include <cstdint>
#include <math.h>

#define TOKENS 2048
#define DIM    512
#define NEXP   16
#define HID    2048
#define NSLOTS (TOKENS*2)
#define TMT    128
#define KC     32
#define MAXT   48
#define TM2    64
#define MAXT2  80
#define NB1    (HID/128)   // 16
#define NB2    (DIM/128)   // 4
// gemm1 (cp.async A, permuted layout)
#define ASTR   40
#define BSTR   136
#define ABYTES (128*ASTR*4)              // 20480
#define SBYTES (ABYTES + KC*BSTR*4)      // 37888
#define SFLOAT (SBYTES/4)
#define AFLOAT (ABYTES/4)
// gemm2 (reg A path, natural layout)
#define ASTR2   36
#define ABY2    (64*ASTR2*4)             // 9216
#define BSTAGE  (KC*BSTR*4)              // 17408
#define SMEM2   (2*ABY2 + 3*BSTAGE)      // 70656

// ---------------- device scratch ----------------
__device__ int   g_cnt[NEXP];
__device__ int   g_list[NEXP*TOKENS];
__device__ float g_wk[NSLOTS];
__device__ int   g_perm[NSLOTS];
__device__ int   g_rowe[NSLOTS];
__device__ float g_mu[NSLOTS], g_rs[NSLOTS];
__device__ float g_psum[NSLOTS*NB1], g_psq[NSLOTS*NB1];
__device__ float g_xr[(size_t)TOKENS*DIM];
__device__ float g_hbuf[(size_t)NSLOTS*HID];

// ---------------- helpers ----------------
__device__ __forceinline__ uint32_t smem_u32(const void* p) {
    uint32_t a;
    asm("{ .reg .u64 t; cvta.to.shared.u64 t, %1; cvt.u32.u64 %0, t; }" : "=r"(a) : "l"(p));
    return a;
}
__device__ __forceinline__ uint32_t tf32r(float x) {
    uint32_t r; asm("cvt.rna.tf32.f32 %0, %1;" : "=r"(r) : "f"(x)); return r;
}
__device__ __forceinline__ float tf32f(float x) { return __uint_as_float(tf32r(x)); }
__device__ __forceinline__ void mma8(float* d, const uint32_t* a, const uint32_t* b) {
    asm volatile("mma.sync.aligned.m16n8k8.row.col.f32.tf32.tf32.f32 "
        "{%0,%1,%2,%3}, {%4,%5,%6,%7}, {%8,%9}, {%0,%1,%2,%3};"
        : "+f"(d[0]), "+f"(d[1]), "+f"(d[2]), "+f"(d[3])
        : "r"(a[0]), "r"(a[1]), "r"(a[2]), "r"(a[3]), "r"(b[0]), "r"(b[1]));
}
__device__ __forceinline__ void cpa16(uint32_t dst, const float* src) {
    asm volatile("cp.async.cg.shared.global [%0], [%1], 16;" :: "r"(dst), "l"(src));
}
#define CP_COMMIT() asm volatile("cp.async.commit_group;" ::: "memory")
#define CP_WAIT1()  asm volatile("cp.async.wait_group 1;" ::: "memory")
__device__ __forceinline__ void sts128(uint32_t a, float x, float y, float z, float w) {
    asm volatile("st.shared.v4.f32 [%0], {%1,%2,%3,%4};" :: "r"(a), "f"(x), "f"(y), "f"(z), "f"(w));
}
__device__ __forceinline__ void redadd(float* p, float v) {
    asm volatile("red.global.add.f32 [%0], %1;" :: "l"(p), "f"(v) : "memory");
}
__device__ __forceinline__ float silu(float v) { return v / (1.f + __expf(-v)); }

// tile -> (expert, gp0, rows); returns false past end
__device__ __forceinline__ bool tilemap(int tile, int TM, int& e, int& gp0, int& rows) {
    int a = 0, tt = tile;
    bool ok = false;
#pragma unroll
    for (int ee = 0; ee < NEXP; ee++) {
        int c = g_cnt[ee];
        int nt = (c + TM - 1) / TM;
        if (!ok) {
            if (tt < nt) { e = ee; gp0 = a + tt * TM; rows = min(TM, c - tt * TM); ok = true; }
            else tt -= nt;
        }
        a += c;
    }
    return ok;
}

// ---------------- small kernels ----------------
// pre-round x to tf32 with 8-group permutation; block 0 zeroes g_cnt
__global__ __launch_bounds__(256) void xcvt_kernel(const float* __restrict__ x) {
    if (blockIdx.x == 0 && threadIdx.x < NEXP) g_cnt[threadIdx.x] = 0;
    int i = blockIdx.x * 256 + threadIdx.x;
    const float4* s = (const float4*)(x + (size_t)i * 8);
    float4 u = s[0], v = s[1];
    float4 o0 = make_float4(tf32f(u.x), tf32f(v.x), tf32f(u.y), tf32f(v.y));
    float4 o1 = make_float4(tf32f(u.z), tf32f(v.z), tf32f(u.w), tf32f(v.w));
    float4* d = (float4*)(g_xr + (size_t)i * 8);
    d[0] = o0; d[1] = o1;
}

__global__ __launch_bounds__(256) void route_kernel(const float* __restrict__ x,
                                                    const float* __restrict__ Wg) {
    int t = (blockIdx.x * blockDim.x + threadIdx.x) >> 5;
    int lane = threadIdx.x & 31;
    if (t >= TOKENS) return;
    const float* xr = x + (size_t)t * DIM;
    float acc = 0.f;
    if (lane < NEXP) {
#pragma unroll 8
        for (int d = 0; d < DIM; d++) acc = fmaf(xr[d], Wg[d * NEXP + lane], acc);
    }
    float v0 = -1e30f, v1 = -1e30f;
    int i0 = 0, i1 = 0;
#pragma unroll
    for (int i = 0; i < NEXP; i++) {
        float vi = __shfl_sync(0xffffffffu, acc, i);
        if (vi > v0)      { v1 = v0; i1 = i0; v0 = vi; i0 = i; }
        else if (vi > v1) { v1 = vi; i1 = i; }
    }
    if (lane == 0) {
        float e1 = __expf(v1 - v0);
        float s  = 1.f + e1;
        g_wk[t * 2 + 0] = 1.f / s;
        g_wk[t * 2 + 1] = e1 / s;
        int p0 = atomicAdd(&g_cnt[i0], 1);
        g_list[i0 * TOKENS + p0] = t * 2 + 0;
        int p1 = atomicAdd(&g_cnt[i1], 1);
        g_list[i1 * TOKENS + p1] = t * 2 + 1;
    }
}

// pure parallel scatter (one block per expert)
__global__ __launch_bounds__(256) void scatter_kernel() {
    int e = blockIdx.x;
    int o = 0;
#pragma unroll
    for (int j = 0; j < NEXP; j++) {
        int cj = g_cnt[j];
        if (j < e) o += cj;
    }
    int c = g_cnt[e];
    for (int i = threadIdx.x; i < c; i += 256) {
        int sl = g_list[e * TOKENS + i];
        g_perm[o + i] = sl;
        g_rowe[o + i] = e;
    }
}

// ---------------- GEMM1: h = silu(xr @ W1 + b1), fused LN partials ----------------
__global__ __launch_bounds__(256, 2) void gemm1_kernel(const float* __restrict__ W1,
                                                       const float* __restrict__ b1) {
    extern __shared__ float dsm[];
    __shared__ int s_tok[TMT];
    int e, gp0, rows;
    if (!tilemap(blockIdx.y, TMT, e, gp0, rows)) return;
    int n0 = blockIdx.x * 128;
    int tid = threadIdx.x, lane = tid & 31, wid = tid >> 5;
    int g = lane >> 2, tg = lane & 3;
    int wm = wid & 1, wn = wid >> 1;
    uint32_t dynb = smem_u32(dsm);

    if (tid < TMT) {
        int r = (tid < rows) ? tid : rows - 1;
        s_tok[tid] = g_perm[gp0 + r] >> 1;
    }
    __syncthreads();

    const float* pA[4]; uint32_t dA[4];
    const float* pB[4]; uint32_t dB[4];
    const float* Wb = W1 + (size_t)e * DIM * HID + n0;
#pragma unroll
    for (int i = 0; i < 4; i++) {
        int c = tid + 256 * i;
        int row = c >> 3, fo = (c & 7) * 4;
        pA[i] = g_xr + (size_t)s_tok[row] * DIM + fo;
        dA[i] = dynb + (uint32_t)(row * (ASTR * 4) + fo * 4);
        int kr = c >> 5, nc = (c & 31) * 4;
        pB[i] = Wb + (size_t)kr * HID + nc;
        dB[i] = dynb + (uint32_t)(ABYTES + kr * (BSTR * 4) + nc * 4);
    }

    float d[4][4][4];
#pragma unroll
    for (int i = 0; i < 4; i++)
#pragma unroll
        for (int j = 0; j < 4; j++)
#pragma unroll
            for (int c = 0; c < 4; c++) d[i][j][c] = 0.f;

    const int S = DIM / KC;   // 16
#pragma unroll
    for (int ps = 0; ps < 2; ps++) {
#pragma unroll
        for (int i = 0; i < 4; i++) {
            cpa16(dA[i] + ps * SBYTES, pA[i] + ps * KC);
            cpa16(dB[i] + ps * SBYTES, pB[i] + (size_t)ps * KC * HID);
        }
        CP_COMMIT();
    }

    int st = 0, si = 2;
    for (int s = 0; s < S; s++) {
        CP_WAIT1();
        __syncthreads();
        if (s + 2 < S) {
            int k0 = (s + 2) * KC;
#pragma unroll
            for (int i = 0; i < 4; i++) {
                cpa16(dA[i] + si * SBYTES, pA[i] + k0);
                cpa16(dB[i] + si * SBYTES, pB[i] + (size_t)k0 * HID);
            }
        }
        CP_COMMIT();
        const float* Ab = dsm + st * SFLOAT;
        const float* Bb = Ab + AFLOAT;
#pragma unroll
        for (int k8 = 0; k8 < KC; k8 += 8) {
            uint32_t af[4][4], bf[4][2];
#pragma unroll
            for (int mf = 0; mf < 4; mf++) {
                const float* ap = Ab + (wm * 64 + mf * 16 + g) * ASTR + k8 + 2 * tg;
                float2 lo = *(const float2*)ap;
                float2 hi = *(const float2*)(ap + 8 * ASTR);
                af[mf][0] = __float_as_uint(lo.x);
                af[mf][1] = __float_as_uint(hi.x);
                af[mf][2] = __float_as_uint(lo.y);
                af[mf][3] = __float_as_uint(hi.y);
            }
#pragma unroll
            for (int nf = 0; nf < 4; nf++) {
                const float* bp = Bb + (k8 + tg) * BSTR + wn * 32 + nf * 8 + g;
                bf[nf][0] = tf32r(bp[0]);
                bf[nf][1] = tf32r(bp[4 * BSTR]);
            }
#pragma unroll
            for (int mf = 0; mf < 4; mf++)
#pragma unroll
                for (int nf = 0; nf < 4; nf++)
                    mma8(d[mf][nf], af[mf], bf[nf]);
        }
        st = (st == 2) ? 0 : st + 1;
        si = (si == 2) ? 0 : si + 1;
    }
    __syncthreads();
    float* s_sum = dsm;
    float* s_sq  = dsm + 512;

    const float* brow = b1 + (size_t)e * HID + n0;
    float bias[4][2];
#pragma unroll
    for (int nf = 0; nf < 4; nf++) {
        int n = wn * 32 + nf * 8 + tg * 2;
        bias[nf][0] = brow[n];
        bias[nf][1] = brow[n + 1];
    }
#pragma unroll
    for (int mf = 0; mf < 4; mf++) {
#pragma unroll
        for (int h = 0; h < 2; h++) {
            int lr = wm * 64 + mf * 16 + g + 8 * h;
            bool val = (lr < rows);
            int gp = gp0 + lr;
            float ss = 0.f, qq = 0.f;
            float* hrow = g_hbuf + (size_t)gp * HID + n0;
#pragma unroll
            for (int nf = 0; nf < 4; nf++) {
                float v0 = silu(d[mf][nf][2 * h + 0] + bias[nf][0]);
                float v1 = silu(d[mf][nf][2 * h + 1] + bias[nf][1]);
                ss += v0 + v1;
                qq += v0 * v0 + v1 * v1;
                if (val) {
                    *(float2*)(hrow + wn * 32 + nf * 8 + tg * 2) = make_float2(v0, v1);
                }
            }
            ss += __shfl_xor_sync(0xffffffffu, ss, 1);
            ss += __shfl_xor_sync(0xffffffffu, ss, 2);
            qq += __shfl_xor_sync(0xffffffffu, qq, 1);
            qq += __shfl_xor_sync(0xffffffffu, qq, 2);
            if (tg == 0) { s_sum[wn * TMT + lr] = ss; s_sq[wn * TMT + lr] = qq; }
        }
    }
    __syncthreads();
    if (tid < TMT && tid < rows) {
        float ts = s_sum[tid] + s_sum[TMT + tid] + s_sum[2 * TMT + tid] + s_sum[3 * TMT + tid];
        float tq = s_sq[tid] + s_sq[TMT + tid] + s_sq[2 * TMT + tid] + s_sq[3 * TMT + tid];
        g_psum[(size_t)(gp0 + tid) * NB1 + blockIdx.x] = ts;
        g_psq [(size_t)(gp0 + tid) * NB1 + blockIdx.x] = tq;
    }
}

// ---------------- lnstats: mu/rs per row (warp per row) ----------------
__global__ __launch_bounds__(256) void lnstats_kernel() {
    int w = (blockIdx.x * blockDim.x + threadIdx.x) >> 5;
    int lane = threadIdx.x & 31;
    if (w >= NSLOTS) return;
    float s = (lane < NB1) ? g_psum[(size_t)w * NB1 + lane] : 0.f;
    float q = (lane < NB1) ? g_psq [(size_t)w * NB1 + lane] : 0.f;
#pragma unroll
    for (int o = 8; o; o >>= 1) {
        s += __shfl_xor_sync(0xffffffffu, s, o);
        q += __shfl_xor_sync(0xffffffffu, q, o);
    }
    if (lane == 0) {
        float mu = s * (1.f / HID);
        float var = q * (1.f / HID) - mu * mu;
        g_mu[w] = mu;
        g_rs[w] = rsqrtf(var + 1e-5f);
    }
}

// ---------------- GEMM2 (TM=64): out += w * ((LN(h)g+b) @ W2 + b2) ----------------
__global__ __launch_bounds__(256, 2) void gemm2_kernel(const float* __restrict__ W2,
                                                       const float* __restrict__ b2,
                                                       const float* __restrict__ ln_g,
                                                       const float* __restrict__ ln_b,
                                                       float* __restrict__ out) {
    extern __shared__ float dsm[];
    __shared__ int s_gp[TM2];
    __shared__ float s_w[TM2];
    int e, gp0, rows;
    if (!tilemap(blockIdx.y, TM2, e, gp0, rows)) return;
    int n0 = blockIdx.x * 128;
    int tid = threadIdx.x, lane = tid & 31, wid = tid >> 5;
    int g = lane >> 2, tg = lane & 3;
    int wm = wid & 1, wn = wid >> 1;
    uint32_t dynb = smem_u32(dsm);

    if (tid < TM2) {
        int r = (tid < rows) ? tid : rows - 1;
        s_gp[tid] = gp0 + r;
        s_w[tid] = (tid < rows) ? g_wk[g_perm[gp0 + tid]] : 0.f;
    }
    __syncthreads();

    // A path: LDG -> LN transform -> tf32 -> STS (2-stage)
    int arow = tid >> 2, kg = tid & 3;
    int agp = s_gp[arow];
    float mu = g_mu[agp], rs = g_rs[agp];
    const float* aP = g_hbuf + (size_t)agp * HID + kg * 8;
    const float* gP = ln_g + (size_t)e * HID + kg * 8;
    const float* lP = ln_b + (size_t)e * HID + kg * 8;
    uint32_t aDst = dynb + (uint32_t)((arow * ASTR2 + kg * 8) * 4);

    // B path: cp.async 3-stage
    const float* pB[4]; uint32_t dB[4];
    const float* Wb = W2 + (size_t)e * HID * DIM + n0;
#pragma unroll
    for (int i = 0; i < 4; i++) {
        int c = tid + 256 * i;
        int kr = c >> 5, nc = (c & 31) * 4;
        pB[i] = Wb + (size_t)kr * DIM + nc;
        dB[i] = dynb + (uint32_t)(2 * ABY2 + kr * (BSTR * 4) + nc * 4);
    }

    float d[2][4][4];
#pragma unroll
    for (int i = 0; i < 2; i++)
#pragma unroll
        for (int j = 0; j < 4; j++)
#pragma unroll
            for (int c = 0; c < 4; c++) d[i][j][c] = 0.f;

    const int S = HID / KC;   // 64
    float4 av0, av1, gv0, gv1, lv0, lv1;
    // prologue: A regs s0; B s0,s1
    av0 = *(const float4*)(aP);     av1 = *(const float4*)(aP + 4);
    gv0 = *(const float4*)(gP);     gv1 = *(const float4*)(gP + 4);
    lv0 = *(const float4*)(lP);     lv1 = *(const float4*)(lP + 4);
#pragma unroll
    for (int ps = 0; ps < 2; ps++) {
#pragma unroll
        for (int i = 0; i < 4; i++)
            cpa16(dB[i] + ps * BSTAGE, pB[i] + (size_t)ps * KC * DIM);
        CP_COMMIT();
    }
    // STS A0
    {
        float t0 = tf32f((av0.x - mu) * rs * gv0.x + lv0.x);
        float t1 = tf32f((av0.y - mu) * rs * gv0.y + lv0.y);
        float t2 = tf32f((av0.z - mu) * rs * gv0.z + lv0.z);
        float t3 = tf32f((av0.w - mu) * rs * gv0.w + lv0.w);
        float t4 = tf32f((av1.x - mu) * rs * gv1.x + lv1.x);
        float t5 = tf32f((av1.y - mu) * rs * gv1.y + lv1.y);
        float t6 = tf32f((av1.z - mu) * rs * gv1.z + lv1.z);
        float t7 = tf32f((av1.w - mu) * rs * gv1.w + lv1.w);
        sts128(aDst, t0, t1, t2, t3);
        sts128(aDst + 16, t4, t5, t6, t7);
    }
    // A regs s1
    av0 = *(const float4*)(aP + KC);     av1 = *(const float4*)(aP + KC + 4);
    gv0 = *(const float4*)(gP + KC);     gv1 = *(const float4*)(gP + KC + 4);
    lv0 = *(const float4*)(lP + KC);     lv1 = *(const float4*)(lP + KC + 4);
    CP_WAIT1();
    __syncthreads();

    int st3 = 0, si3 = 2;
    for (int s = 0; s < S; s++) {
        // STS A(s+1) into buf (s+1)&1
        if (s + 1 < S) {
            float t0 = tf32f((av0.x - mu) * rs * gv0.x + lv0.x);
            float t1 = tf32f((av0.y - mu) * rs * gv0.y + lv0.y);
            float t2 = tf32f((av0.z - mu) * rs * gv0.z + lv0.z);
            float t3 = tf32f((av0.w - mu) * rs * gv0.w + lv0.w);
            float t4 = tf32f((av1.x - mu) * rs * gv1.x + lv1.x);
            float t5 = tf32f((av1.y - mu) * rs * gv1.y + lv1.y);
            float t6 = tf32f((av1.z - mu) * rs * gv1.z + lv1.z);
            float t7 = tf32f((av1.w - mu) * rs * gv1.w + lv1.w);
            uint32_t ad = aDst + (uint32_t)(((s + 1) & 1) * ABY2);
            sts128(ad, t0, t1, t2, t3);
            sts128(ad + 16, t4, t5, t6, t7);
        }
        // LDG A(s+2)
        if (s + 2 < S) {
            int k0 = (s + 2) * KC;
            av0 = *(const float4*)(aP + k0);     av1 = *(const float4*)(aP + k0 + 4);
            gv0 = *(const float4*)(gP + k0);     gv1 = *(const float4*)(gP + k0 + 4);
            lv0 = *(const float4*)(lP + k0);     lv1 = *(const float4*)(lP + k0 + 4);
        }
        // B cp.async (s+2)
        if (s + 2 < S) {
            int k0 = (s + 2) * KC;
#pragma unroll
            for (int i = 0; i < 4; i++)
                cpa16(dB[i] + si3 * BSTAGE, pB[i] + (size_t)k0 * DIM);
        }
        CP_COMMIT();
        // MMA on stage s
        const float* Ab = dsm + (s & 1) * (ABY2 / 4);
        const float* Bb = dsm + (2 * ABY2) / 4 + st3 * (BSTAGE / 4);
#pragma unroll
        for (int k8 = 0; k8 < KC; k8 += 8) {
            uint32_t af[2][4], bf[4][2];
#pragma unroll
            for (int mf = 0; mf < 2; mf++) {
                const float* ap = Ab + (wm * 32 + mf * 16 + g) * ASTR2 + k8 + tg;
                af[mf][0] = __float_as_uint(ap[0]);
                af[mf][1] = __float_as_uint(ap[8 * ASTR2]);
                af[mf][2] = __float_as_uint(ap[4]);
                af[mf][3] = __float_as_uint(ap[8 * ASTR2 + 4]);
            }
#pragma unroll
            for (int nf = 0; nf < 4; nf++) {
                const float* bp = Bb + (k8 + tg) * BSTR + wn * 32 + nf * 8 + g;
                bf[nf][0] = tf32r(bp[0]);
                bf[nf][1] = tf32r(bp[4 * BSTR]);
            }
#pragma unroll
            for (int mf = 0; mf < 2; mf++)
#pragma unroll
                for (int nf = 0; nf < 4; nf++)
                    mma8(d[mf][nf], af[mf], bf[nf]);
        }
        st3 = (st3 == 2) ? 0 : st3 + 1;
        si3 = (si3 == 2) ? 0 : si3 + 1;
        CP_WAIT1();
        __syncthreads();
    }

    const float* brow = b2 + (size_t)e * DIM + n0;
    float bias[4][2];
#pragma unroll
    for (int nf = 0; nf < 4; nf++) {
        int n = wn * 32 + nf * 8 + tg * 2;
        bias[nf][0] = brow[n];
        bias[nf][1] = brow[n + 1];
    }
#pragma unroll
    for (int mf = 0; mf < 2; mf++) {
#pragma unroll
        for (int h = 0; h < 2; h++) {
            int lr = wm * 32 + mf * 16 + g + 8 * h;
            if (lr >= rows) continue;
            int slot = g_perm[gp0 + lr];
            float w = s_w[lr];
            float* orow = out + (size_t)(slot >> 1) * DIM + n0 + wn * 32 + tg * 2;
#pragma unroll
            for (int nf = 0; nf < 4; nf++) {
                float v0 = (d[mf][nf][2 * h + 0] + bias[nf][0]) * w;
                float v1 = (d[mf][nf][2 * h + 1] + bias[nf][1]) * w;
                redadd(orow + nf * 8, v0);
                redadd(orow + nf * 8 + 1, v1);
            }
        }
    }
}

extern "C" void kernel_launch(void* const* d_in, const int* in_sizes, int n_in,
                              void* d_out, int out_size) {
    const float* x    = (const float*)d_in[0];
    const float* Wg   = (const float*)d_in[1];
    const float* W1   = (const float*)d_in[2];
    const float* b1   = (const float*)d_in[3];
    const float* ln_g = (const float*)d_in[4];
    const float* ln_b = (const float*)d_in[5];
    const float* W2   = (const float*)d_in[6];
    const float* b2   = (const float*)d_in[7];
    float* out = (float*)d_out;

    cudaFuncSetAttribute(gemm1_kernel, cudaFuncAttributeMaxDynamicSharedMemorySize, 3 * SBYTES);
    cudaFuncSetAttribute(gemm2_kernel, cudaFuncAttributeMaxDynamicSharedMemorySize, SMEM2);

    cudaMemsetAsync(out, 0, (size_t)out_size * sizeof(float));
    xcvt_kernel<<<TOKENS * DIM / 8 / 256, 256>>>(x);
    route_kernel<<<(TOKENS * 32 + 255) / 256, 256>>>(x, Wg);
    scatter_kernel<<<NEXP, 256>>>();
    gemm1_kernel<<<dim3(NB1, MAXT), 256, 3 * SBYTES>>>(W1, b1);
    lnstats_kernel<<<NSLOTS * 32 / 256, 256>>>();
    gemm2_kernel<<<dim3(NB2, MAXT2), 256, SMEM2>>>(W2, b2, ln_g, ln_b, out);
}